// round 7
// baseline (speedup 1.0000x reference)
#include <cuda_runtime.h>
#include <cuda_bf16.h>
#include <cstdint>

#define NN 100000
#define EE 1600000
#define IN_F 128
#define HID_F 256
#define OUT_F 47
#define T2S 48

// ---------------- scratch ---------------------------------------------------
__device__ float g_h [(size_t)NN * HID_F];          // fp32 h; reused as layer2 tmp
__device__ float g_t2[(size_t)NN * T2S];
__device__ __align__(16) __nv_bfloat16 g_xh [(size_t)NN * IN_F];
__device__ __align__(16) __nv_bfloat16 g_xl [(size_t)NN * IN_F];
__device__ __align__(16) __nv_bfloat16 g_aggh[(size_t)NN * HID_F];
__device__ __align__(16) __nv_bfloat16 g_aggl[(size_t)NN * HID_F];
__device__ __align__(16) __nv_bfloat16 g_hh [(size_t)NN * HID_F];
__device__ __align__(16) __nv_bfloat16 g_hl [(size_t)NN * HID_F];
__device__ __align__(16) __nv_bfloat16 g_h2h[(size_t)NN * HID_F];
__device__ __align__(16) __nv_bfloat16 g_h2l[(size_t)NN * HID_F];
__device__ int   g_count [NN];
__device__ float g_invdeg[NN];
__device__ int   g_rowptr[NN + 1];
__device__ int   g_cursor[NN];
__device__ int   g_csrsrc[EE];
__device__ int   g_bsums [128];
__device__ int   g_is64;

// weight tables, bf16 hi/lo, transposed [N,K] row-major
#define WB_TOTAL 229376
__device__ __align__(16) __nv_bfloat16 g_wbhi[WB_TOTAL];
__device__ __align__(16) __nv_bfloat16 g_wblo[WB_TOTAL];

// ---------------- prep ------------------------------------------------------
__global__ void k_prep(const int* ei_raw,
                       const float* Wl0, const float* Wr0,
                       const float* Wl1, const float* Wr1,
                       const float* Wl2, const float* Wr2) {
    int idx = blockIdx.x * blockDim.x + threadIdx.x;
    if (idx < NN) g_count[idx] = 0;
    if (idx == 0) {
        int is64 = 1;
        for (int i = 0; i < 256; i++)
            if (ei_raw[2 * i + 1] != 0) { is64 = 0; break; }
        g_is64 = is64;
    }
    if (idx < WB_TOTAL) {
        float w;
        if (idx < 32768)       { int l = idx;          int n = l >> 7, k = l & 127; w = Wl0[k * 256 + n]; }
        else if (idx < 65536)  { int l = idx - 32768;  int n = l >> 7, k = l & 127; w = Wr0[k * 256 + n]; }
        else if (idx < 131072) { int l = idx - 65536;  int n = l >> 8, k = l & 255; w = Wl1[k * 256 + n]; }
        else if (idx < 196608) { int l = idx - 131072; int n = l >> 8, k = l & 255; w = Wr1[k * 256 + n]; }
        else if (idx < 212992) { int l = idx - 196608; int n = l >> 8, k = l & 255; w = (n < OUT_F) ? Wl2[k * OUT_F + n] : 0.f; }
        else                   { int l = idx - 212992; int n = l >> 8, k = l & 255; w = (n < OUT_F) ? Wr2[k * OUT_F + n] : 0.f; }
        __nv_bfloat16 hi = __float2bfloat16(w);
        __nv_bfloat16 lo = __float2bfloat16(w - __bfloat162float(hi));
        g_wbhi[idx] = hi;
        g_wblo[idx] = lo;
    }
}

// x fp32 -> hi/lo planes
__global__ void k_cvt(const float4* __restrict__ X, __nv_bfloat162* __restrict__ H,
                      __nv_bfloat162* __restrict__ L, int n4) {
    int i = blockIdx.x * blockDim.x + threadIdx.x;
    if (i >= n4) return;
    float4 v = X[i];
    __nv_bfloat16 h0 = __float2bfloat16(v.x), h1 = __float2bfloat16(v.y);
    __nv_bfloat16 h2 = __float2bfloat16(v.z), h3 = __float2bfloat16(v.w);
    __nv_bfloat162 a, b, c, d;
    a.x = h0; a.y = h1; b.x = h2; b.y = h3;
    c.x = __float2bfloat16(v.x - __bfloat162float(h0));
    c.y = __float2bfloat16(v.y - __bfloat162float(h1));
    d.x = __float2bfloat16(v.z - __bfloat162float(h2));
    d.y = __float2bfloat16(v.w - __bfloat162float(h3));
    H[2 * i] = a; H[2 * i + 1] = b;
    L[2 * i] = c; L[2 * i + 1] = d;
}

// ---------------- CSR build -------------------------------------------------
__device__ __forceinline__ int load_edge(const void* ei, long long idx, int is64) {
    if (is64) return (int)((const long long*)ei)[idx];
    return ((const int*)ei)[idx];
}

__global__ void k_hist(const void* ei) {
    int e = blockIdx.x * blockDim.x + threadIdx.x;
    if (e < EE) {
        int d = load_edge(ei, (long long)EE + e, g_is64);
        atomicAdd(&g_count[d], 1);
    }
}

__global__ void k_scan1() {
    __shared__ int sh[1024];
    int i = blockIdx.x * 1024 + threadIdx.x;
    int v = (i < NN) ? g_count[i] : 0;
    sh[threadIdx.x] = v;
    __syncthreads();
    for (int off = 1; off < 1024; off <<= 1) {
        int t = (threadIdx.x >= off) ? sh[threadIdx.x - off] : 0;
        __syncthreads();
        sh[threadIdx.x] += t;
        __syncthreads();
    }
    if (i < NN) g_rowptr[i] = sh[threadIdx.x] - v;
    if (threadIdx.x == 1023) g_bsums[blockIdx.x] = sh[1023];
}

__global__ void k_scan23() {
    __shared__ int base;
    if (threadIdx.x == 0) {
        int run = 0;
        for (int b = 0; b < (int)blockIdx.x; b++) run += g_bsums[b];
        base = run;
    }
    __syncthreads();
    int i = blockIdx.x * 1024 + threadIdx.x;
    if (i < NN) {
        int r = g_rowptr[i] + base;
        g_rowptr[i] = r;
        g_cursor[i] = r;
        g_invdeg[i] = 1.0f / (float)max(g_count[i], 1);
    }
    if (i == 0) g_rowptr[NN] = EE;
}

__global__ void k_scatter(const void* ei) {
    int e = blockIdx.x * blockDim.x + threadIdx.x;
    if (e < EE) {
        int is64 = g_is64;
        int d = load_edge(ei, (long long)EE + e, is64);
        int s = load_edge(ei, e, is64);
        int p = atomicAdd(&g_cursor[d], 1);
        g_csrsrc[p] = s;
    }
}

// ---------------- mean aggregation -> bf16 hi/lo planes ----------------------
template <int NV>
__global__ void k_agg_planes(const float* __restrict__ X,
                             __nv_bfloat16* __restrict__ OH, __nv_bfloat16* __restrict__ OL) {
    int w = (blockIdx.x * blockDim.x + threadIdx.x) >> 5;
    int lane = threadIdx.x & 31;
    if (w >= NN) return;
    int beg = g_rowptr[w], end = g_rowptr[w + 1];
    const int Wd = NV * 128;
    float4 acc[NV];
#pragma unroll
    for (int v = 0; v < NV; v++) acc[v] = make_float4(0.f, 0.f, 0.f, 0.f);
    int e = beg;
    for (; e + 4 <= end; e += 4) {
        int s0 = g_csrsrc[e], s1 = g_csrsrc[e + 1];
        int s2 = g_csrsrc[e + 2], s3 = g_csrsrc[e + 3];
        const float4* r0 = (const float4*)(X + (size_t)s0 * Wd);
        const float4* r1 = (const float4*)(X + (size_t)s1 * Wd);
        const float4* r2 = (const float4*)(X + (size_t)s2 * Wd);
        const float4* r3 = (const float4*)(X + (size_t)s3 * Wd);
#pragma unroll
        for (int v = 0; v < NV; v++) {
            float4 t0 = r0[lane + 32 * v];
            float4 t1 = r1[lane + 32 * v];
            float4 t2 = r2[lane + 32 * v];
            float4 t3 = r3[lane + 32 * v];
            acc[v].x += t0.x + t1.x + t2.x + t3.x;
            acc[v].y += t0.y + t1.y + t2.y + t3.y;
            acc[v].z += t0.z + t1.z + t2.z + t3.z;
            acc[v].w += t0.w + t1.w + t2.w + t3.w;
        }
    }
    for (; e < end; e++) {
        int s = g_csrsrc[e];
        const float4* row = (const float4*)(X + (size_t)s * Wd);
#pragma unroll
        for (int v = 0; v < NV; v++) {
            float4 t = row[lane + 32 * v];
            acc[v].x += t.x; acc[v].y += t.y; acc[v].z += t.z; acc[v].w += t.w;
        }
    }
    float inv = g_invdeg[w];
#pragma unroll
    for (int v = 0; v < NV; v++) {
        float4 a = acc[v];
        a.x *= inv; a.y *= inv; a.z *= inv; a.w *= inv;
        __nv_bfloat16 h0 = __float2bfloat16(a.x), h1 = __float2bfloat16(a.y);
        __nv_bfloat16 h2 = __float2bfloat16(a.z), h3 = __float2bfloat16(a.w);
        __nv_bfloat162 p0, p1, q0, q1;
        p0.x = h0; p0.y = h1; p1.x = h2; p1.y = h3;
        q0.x = __float2bfloat16(a.x - __bfloat162float(h0));
        q0.y = __float2bfloat16(a.y - __bfloat162float(h1));
        q1.x = __float2bfloat16(a.z - __bfloat162float(h2));
        q1.y = __float2bfloat16(a.w - __bfloat162float(h3));
        int col = (lane + 32 * v) * 4;
        *(__nv_bfloat162*)(OH + (size_t)w * Wd + col)     = p0;
        *(__nv_bfloat162*)(OH + (size_t)w * Wd + col + 2) = p1;
        *(__nv_bfloat162*)(OL + (size_t)w * Wd + col)     = q0;
        *(__nv_bfloat162*)(OL + (size_t)w * Wd + col + 2) = q1;
    }
}

// mean-agg over t2 (stride T2S) + tmp add -> out (stride 47)
__global__ void k_agg47_add(const float* __restrict__ T2, const float* __restrict__ Tmp,
                            float* __restrict__ out) {
    int w = (blockIdx.x * blockDim.x + threadIdx.x) >> 5;
    int lane = threadIdx.x & 31;
    if (w >= NN) return;
    int beg = g_rowptr[w], end = g_rowptr[w + 1];
    float a0 = 0.f, a1 = 0.f;
    int e = beg;
    for (; e + 4 <= end; e += 4) {
        int s0 = g_csrsrc[e], s1 = g_csrsrc[e + 1];
        int s2 = g_csrsrc[e + 2], s3 = g_csrsrc[e + 3];
        const float* r0 = T2 + (size_t)s0 * T2S;
        const float* r1 = T2 + (size_t)s1 * T2S;
        const float* r2 = T2 + (size_t)s2 * T2S;
        const float* r3 = T2 + (size_t)s3 * T2S;
        a0 += r0[lane] + r1[lane] + r2[lane] + r3[lane];
        if (lane < OUT_F - 32)
            a1 += r0[lane + 32] + r1[lane + 32] + r2[lane + 32] + r3[lane + 32];
    }
    for (; e < end; e++) {
        const float* row = T2 + (size_t)g_csrsrc[e] * T2S;
        a0 += row[lane];
        if (lane < OUT_F - 32) a1 += row[lane + 32];
    }
    float inv = g_invdeg[w];
    const float* tr = Tmp + (size_t)w * T2S;
    float* orow = out + (size_t)w * OUT_F;
    orow[lane] = a0 * inv + tr[lane];
    if (lane < OUT_F - 32) orow[lane + 32] = a1 * inv + tr[lane + 32];
}

// ---------------- GEMM: bf16 planes, cp.async, 64x64 warp tiles -------------
// BN=256: 256 threads, 8 warps (2 M x 4 N), CTA tile 128x256, grid.y=1 -> A read once.
// BN=128: 128 threads, 4 warps (2 M x 2 N).
__device__ __forceinline__ void mma16816(float* c, const uint32_t* a, const uint32_t* b) {
    asm volatile(
        "mma.sync.aligned.m16n8k16.row.col.f32.bf16.bf16.f32 "
        "{%0,%1,%2,%3}, {%4,%5,%6,%7}, {%8,%9}, {%0,%1,%2,%3};"
        : "+f"(c[0]), "+f"(c[1]), "+f"(c[2]), "+f"(c[3])
        : "r"(a[0]), "r"(a[1]), "r"(a[2]), "r"(a[3]), "r"(b[0]), "r"(b[1]));
}
__device__ __forceinline__ void cp16(uint32_t dst, const void* src) {
    asm volatile("cp.async.cg.shared.global [%0], [%1], 16;" :: "r"(dst), "l"(src));
}
__device__ __forceinline__ void cp_commit() {
    asm volatile("cp.async.commit_group;" ::: "memory");
}
template <int N> __device__ __forceinline__ void cp_wait() {
    asm volatile("cp.async.wait_group %0;" :: "n"(N) : "memory");
}
__device__ __forceinline__ uint32_t smem_u32(const void* p) {
    uint32_t a;
    asm("{ .reg .u64 t; cvta.to.shared.u64 t, %1; cvt.u32.u64 %0, t; }"
        : "=r"(a) : "l"(p));
    return a;
}

#define APL 10240   // A plane: 128 rows x 80B

template <int BN, bool DUAL, bool BIAS, bool RELU, bool WF32, bool WPLANES, bool WPRE, bool SPLIT2>
__global__ void __launch_bounds__(BN, BN == 128 ? 2 : 1)
k_mma(const __nv_bfloat16* __restrict__ A1h, const __nv_bfloat16* __restrict__ A1l, int ldA1, int K1,
      const __nv_bfloat16* __restrict__ B1h, const __nv_bfloat16* __restrict__ B1l, int ldB1,
      const __nv_bfloat16* __restrict__ A2h, const __nv_bfloat16* __restrict__ A2l, int ldA2, int K2,
      const __nv_bfloat16* __restrict__ B2h, const __nv_bfloat16* __restrict__ B2l, int ldB2,
      const float* __restrict__ bias,
      float* __restrict__ Cf32, __nv_bfloat16* __restrict__ Ch, __nv_bfloat16* __restrict__ Cl,
      int ldC, float* __restrict__ Cpre, float* __restrict__ Caux, int M) {
    constexpr int ASTR = 40;                 // bf16 units (80 B row stride)
    constexpr int NTN  = BN / 64;            // warps along N
    constexpr int BPL  = BN * 80;            // B plane bytes
    constexpr int STAGE = 2 * APL + 2 * BPL;
    constexpr int A_CPS = 1024;              // 2 planes * 128 rows * 4
    constexpr int B_CPS = 8 * BN;            // 2 planes * BN rows * 4
    extern __shared__ __align__(16) char smem[];
    const uint32_t sbase = smem_u32(smem);

    const int tid  = threadIdx.x;
    const int wid  = tid >> 5;
    const int lane = tid & 31;
    const int wm   = wid / NTN;              // 2 warps along M
    const int wn   = wid % NTN;
    const int gid  = lane >> 2;
    const int tig  = lane & 3;

    const int rowBase = blockIdx.x * 128;
    const int colBlk  = blockIdx.y * BN;

    float acc[4][8][4];
#pragma unroll
    for (int mt = 0; mt < 4; mt++)
#pragma unroll
        for (int nt = 0; nt < 8; nt++)
#pragma unroll
            for (int j = 0; j < 4; j++) acc[mt][nt][j] = 0.f;

    const int NC1 = K1 / 32;
    const int NC  = DUAL ? NC1 + K2 / 32 : NC1;

    auto issue = [&](int c) {
        const uint32_t sb = sbase + (c & 1) * STAGE;
        const int seg = (DUAL && c >= NC1) ? 1 : 0;
        const int k0 = (c - (seg ? NC1 : 0)) * 32;
        const __nv_bfloat16* Ah = seg ? A2h : A1h;
        const __nv_bfloat16* Al = seg ? A2l : A1l;
        const __nv_bfloat16* Bh = seg ? B2h : B1h;
        const __nv_bfloat16* Bl = seg ? B2l : B1l;
        const int ldA = seg ? ldA2 : ldA1;
        const int ldB = seg ? ldB2 : ldB1;
#pragma unroll
        for (int i = tid; i < A_CPS + B_CPS; i += BN) {
            if (i < A_CPS) {
                int p = i >> 9, r = (i >> 2) & 127, ch = i & 3;
                int gr = min(rowBase + r, M - 1);
                const __nv_bfloat16* g = (p ? Al : Ah) + (size_t)gr * ldA + k0 + ch * 8;
                cp16(sb + p * APL + r * 80 + ch * 16, g);
            } else {
                int j = i - A_CPS;
                int p = j / (4 * BN), r = (j >> 2) % BN, ch = j & 3;
                const __nv_bfloat16* g = (p ? Bl : Bh) + (size_t)(colBlk + r) * ldB + k0 + ch * 8;
                cp16(sb + 2 * APL + p * BPL + r * 80 + ch * 16, g);
            }
        }
        cp_commit();
    };

    issue(0);
    for (int c = 0; c < NC; c++) {
        if (c + 1 < NC) { issue(c + 1); cp_wait<1>(); }
        else            { cp_wait<0>(); }
        __syncthreads();
        const char* S = smem + (c & 1) * STAGE;
        const __nv_bfloat16* Ahi = (const __nv_bfloat16*)(S);
        const __nv_bfloat16* Alo = (const __nv_bfloat16*)(S + APL);
        const __nv_bfloat16* Bhi = (const __nv_bfloat16*)(S + 2 * APL);
        const __nv_bfloat16* Blo = (const __nv_bfloat16*)(S + 2 * APL + BPL);
#pragma unroll
        for (int pass = 0; pass < 3; pass++) {
            const __nv_bfloat16* As = (pass == 2) ? Alo : Ahi;
            const __nv_bfloat16* Bs = (pass == 1) ? Blo : Bhi;
#pragma unroll
            for (int ks = 0; ks < 2; ks++) {
                const int kb = ks * 16;
                uint32_t a[4][4];
#pragma unroll
                for (int mt = 0; mt < 4; mt++) {
                    int r0 = 64 * wm + mt * 16 + gid;
                    const uint32_t* ap  = (const uint32_t*)(As + r0 * ASTR + kb);
                    const uint32_t* ap8 = (const uint32_t*)(As + (r0 + 8) * ASTR + kb);
                    a[mt][0] = ap[tig];
                    a[mt][1] = ap8[tig];
                    a[mt][2] = ap[tig + 4];
                    a[mt][3] = ap8[tig + 4];
                }
                uint32_t b[8][2];
#pragma unroll
                for (int nt = 0; nt < 8; nt++) {
                    int br = 64 * wn + nt * 8 + gid;
                    const uint32_t* bp = (const uint32_t*)(Bs + br * ASTR + kb);
                    b[nt][0] = bp[tig];
                    b[nt][1] = bp[tig + 4];
                }
#pragma unroll
                for (int mt = 0; mt < 4; mt++)
#pragma unroll
                    for (int nt = 0; nt < 8; nt++)
                        mma16816(acc[mt][nt], a[mt], b[nt]);
            }
        }
        __syncthreads();
    }

    // ---- epilogue ----
#pragma unroll
    for (int mt = 0; mt < 4; mt++) {
        int r0 = rowBase + 64 * wm + mt * 16 + gid;
#pragma unroll
        for (int nt = 0; nt < 8; nt++) {
            int gc = colBlk + 64 * wn + nt * 8 + 2 * tig;
#pragma unroll
            for (int half = 0; half < 2; half++) {
                int rr = r0 + half * 8;
                if (rr >= M) continue;
                float v0 = acc[mt][nt][half * 2 + 0];
                float v1 = acc[mt][nt][half * 2 + 1];
                if (SPLIT2) {
#pragma unroll
                    for (int q = 0; q < 2; q++) {
                        int col = gc + q;
                        float v = q ? v1 : v0;
                        if (col < 64) {
                            if (col < OUT_F) Cf32[(size_t)rr * T2S + col] = v;
                        } else {
                            int c2 = col - 64;
                            if (c2 < OUT_F) Caux[(size_t)rr * T2S + c2] = v + bias[c2];
                        }
                    }
                } else {
                    if (BIAS) { v0 += bias[gc]; v1 += bias[gc + 1]; }
                    if (WPRE) {
                        float* p = Cpre + (size_t)rr * ldC + gc;
                        p[0] = v0; p[1] = v1;
                    }
                    if (RELU) { v0 = fmaxf(v0, 0.f); v1 = fmaxf(v1, 0.f); }
                    if (WF32)
                        *(float2*)(Cf32 + (size_t)rr * ldC + gc) = make_float2(v0, v1);
                    if (WPLANES) {
                        __nv_bfloat16 h0 = __float2bfloat16(v0);
                        __nv_bfloat16 h1 = __float2bfloat16(v1);
                        __nv_bfloat162 hp; hp.x = h0; hp.y = h1;
                        *(__nv_bfloat162*)(Ch + (size_t)rr * ldC + gc) = hp;
                        __nv_bfloat162 lp;
                        lp.x = __float2bfloat16(v0 - __bfloat162float(h0));
                        lp.y = __float2bfloat16(v1 - __bfloat162float(h1));
                        *(__nv_bfloat162*)(Cl + (size_t)rr * ldC + gc) = lp;
                    }
                }
            }
        }
    }
}

// ---------------- launch ----------------------------------------------------
extern "C" void kernel_launch(void* const* d_in, const int* in_sizes, int n_in,
                              void* d_out, int out_size) {
    const float* x   = (const float*)d_in[0];
    const void*  ei  = d_in[1];
    const float* Wl0 = (const float*)d_in[2];
    const float* bl0 = (const float*)d_in[3];
    const float* Wr0 = (const float*)d_in[4];
    const float* Wl1 = (const float*)d_in[5];
    const float* bl1 = (const float*)d_in[6];
    const float* Wr1 = (const float*)d_in[7];
    const float* Wl2 = (const float*)d_in[8];
    const float* bl2 = (const float*)d_in[9];
    const float* Wr2 = (const float*)d_in[10];

    float* out  = (float*)d_out;
    float* hout = out + (size_t)NN * OUT_F;

    float *p_h, *p_t2;
    __nv_bfloat16 *xh, *xl, *ah, *al, *hh, *hl, *h2h, *h2l, *wbh, *wbl;
    cudaGetSymbolAddress((void**)&p_h,  g_h);
    cudaGetSymbolAddress((void**)&p_t2, g_t2);
    cudaGetSymbolAddress((void**)&xh,  g_xh);
    cudaGetSymbolAddress((void**)&xl,  g_xl);
    cudaGetSymbolAddress((void**)&ah,  g_aggh);
    cudaGetSymbolAddress((void**)&al,  g_aggl);
    cudaGetSymbolAddress((void**)&hh,  g_hh);
    cudaGetSymbolAddress((void**)&hl,  g_hl);
    cudaGetSymbolAddress((void**)&h2h, g_h2h);
    cudaGetSymbolAddress((void**)&h2l, g_h2l);
    cudaGetSymbolAddress((void**)&wbh, g_wbhi);
    cudaGetSymbolAddress((void**)&wbl, g_wblo);

    const int SM256 = 2 * (2 * APL + 2 * 256 * 80);   // 122880
    const int SM128 = 2 * (2 * APL + 2 * 128 * 80);   // 81920
    cudaFuncSetAttribute(k_mma<256, true,  true, true,  true,  true,  false, false>,
                         cudaFuncAttributeMaxDynamicSharedMemorySize, SM256);
    cudaFuncSetAttribute(k_mma<256, true,  true, true,  false, true,  true,  false>,
                         cudaFuncAttributeMaxDynamicSharedMemorySize, SM256);
    cudaFuncSetAttribute(k_mma<128, false, true, false, false, false, false, true>,
                         cudaFuncAttributeMaxDynamicSharedMemorySize, SM128);

    const int MT = (NN + 127) / 128;               // 782
    const int AGG_BLKS = (NN + 7) / 8;

    // CSR build first so the ncu capture slot lands on the first aggregation
    k_prep<<<(WB_TOTAL + 255) / 256, 256>>>((const int*)ei, Wl0, Wr0, Wl1, Wr1, Wl2, Wr2);
    k_hist<<<(EE + 255) / 256, 256>>>(ei);
    k_scan1<<<(NN + 1023) / 1024, 1024>>>();
    k_scan23<<<(NN + 1023) / 1024, 1024>>>();
    k_scatter<<<(EE + 255) / 256, 256>>>(ei);

    // layer 0 aggregation (profile target)
    k_agg_planes<1><<<AGG_BLKS, 256>>>(x, ah, al);
    // x planes (independent; needed before gemm0)
    k_cvt<<<(NN * IN_F / 4 + 255) / 256, 256>>>((const float4*)x,
        (__nv_bfloat162*)xh, (__nv_bfloat162*)xl, NN * IN_F / 4);

    // layer 0: relu(agg(x)@Wl0 + bl0 + x@Wr0) -> g_h fp32 + h planes
    k_mma<256, true, true, true, true, true, false, false><<<dim3(MT, 1), 256, SM256>>>(
        ah, al, IN_F, IN_F, wbh + 0,     wbl + 0,     IN_F,
        xh, xl, IN_F, IN_F, wbh + 32768, wbl + 32768, IN_F,
        bl0, p_h, hh, hl, HID_F, nullptr, nullptr, NN);

    // layer 1: pre -> hout; relu -> h2 planes
    k_agg_planes<2><<<AGG_BLKS, 256>>>(p_h, ah, al);
    k_mma<256, true, true, true, false, true, true, false><<<dim3(MT, 1), 256, SM256>>>(
        ah, al, HID_F, HID_F, wbh + 65536,  wbl + 65536,  HID_F,
        hh, hl, HID_F, HID_F, wbh + 131072, wbl + 131072, HID_F,
        bl1, nullptr, h2h, h2l, HID_F, hout, nullptr, NN);

    // layer 2 fused: t2 = h2@Wl2 ; tmp = h2@Wr2 + bl2 (tmp stored in g_h)
    k_mma<128, false, true, false, false, false, false, true><<<dim3(MT, 1), 128, SM128>>>(
        h2h, h2l, HID_F, HID_F, wbh + 196608, wbl + 196608, HID_F,
        nullptr, nullptr, 0, 0, nullptr, nullptr, 0,
        bl2, p_t2, nullptr, nullptr, T2S, nullptr, p_h, NN);
    // out = mean-agg(t2) + tmp
    k_agg47_add<<<AGG_BLKS, 256>>>(p_t2, p_h, out);
}

// round 8
// speedup vs baseline: 1.6053x; 1.6053x over previous
#include <cuda_runtime.h>
#include <cuda_fp16.h>
#include <cstdint>

#define NN 100000
#define EE 1600000
#define IN_F 128
#define HID_F 256
#define OUT_F 47
#define T2S 48

// ---------------- scratch ---------------------------------------------------
__device__ float g_tmp[(size_t)NN * T2S];           // layer-2 direct term (fp32)
__device__ __align__(16) __half g_xf  [(size_t)NN * IN_F];
__device__ __align__(16) __half g_aggf[(size_t)NN * HID_F];
__device__ __align__(16) __half g_hf  [(size_t)NN * HID_F];
__device__ __align__(16) __half g_h2f [(size_t)NN * HID_F];
__device__ __align__(16) __half g_t2  [(size_t)NN * T2S];
__device__ int   g_count [NN];
__device__ float g_invdeg[NN];
__device__ int   g_rowptr[NN + 1];
__device__ int   g_cursor[NN];
__device__ int   g_csrsrc[EE];
__device__ int   g_bsums [128];
__device__ int   g_is64;

// weight tables, fp16 hi/lo, transposed [N,K] row-major
// B0l 0 (256x128), B0r 32768, B1l 65536 (256x256), B1r 131072,
// B2 combined 196608 (128x256: rows 0-63 = Wl2, 64-127 = Wr2)
#define WB_TOTAL 229376
__device__ __align__(16) __half g_wfh[WB_TOTAL];
__device__ __align__(16) __half g_wfl[WB_TOTAL];

// ---------------- prep ------------------------------------------------------
__global__ void k_prep(const int* ei_raw,
                       const float* Wl0, const float* Wr0,
                       const float* Wl1, const float* Wr1,
                       const float* Wl2, const float* Wr2) {
    int idx = blockIdx.x * blockDim.x + threadIdx.x;
    if (idx < NN) g_count[idx] = 0;
    if (idx == 0) {
        int is64 = 1;
        for (int i = 0; i < 256; i++)
            if (ei_raw[2 * i + 1] != 0) { is64 = 0; break; }
        g_is64 = is64;
    }
    if (idx < WB_TOTAL) {
        float w;
        if (idx < 32768)       { int l = idx;          int n = l >> 7, k = l & 127; w = Wl0[k * 256 + n]; }
        else if (idx < 65536)  { int l = idx - 32768;  int n = l >> 7, k = l & 127; w = Wr0[k * 256 + n]; }
        else if (idx < 131072) { int l = idx - 65536;  int n = l >> 8, k = l & 255; w = Wl1[k * 256 + n]; }
        else if (idx < 196608) { int l = idx - 131072; int n = l >> 8, k = l & 255; w = Wr1[k * 256 + n]; }
        else if (idx < 212992) { int l = idx - 196608; int n = l >> 8, k = l & 255; w = (n < OUT_F) ? Wl2[k * OUT_F + n] : 0.f; }
        else                   { int l = idx - 212992; int n = l >> 8, k = l & 255; w = (n < OUT_F) ? Wr2[k * OUT_F + n] : 0.f; }
        __half hi = __float2half_rn(w);
        __half lo = __float2half_rn(w - __half2float(hi));
        g_wfh[idx] = hi;
        g_wfl[idx] = lo;
    }
}

// x fp32 -> fp16 plane
__global__ void k_cvt(const float4* __restrict__ X, uint2* __restrict__ O, int n4) {
    int i = blockIdx.x * blockDim.x + threadIdx.x;
    if (i >= n4) return;
    float4 v = X[i];
    __half2 p0 = __floats2half2_rn(v.x, v.y);
    __half2 p1 = __floats2half2_rn(v.z, v.w);
    uint2 o;
    o.x = *(uint32_t*)&p0;
    o.y = *(uint32_t*)&p1;
    O[i] = o;
}

// ---------------- CSR build -------------------------------------------------
__device__ __forceinline__ int load_edge(const void* ei, long long idx, int is64) {
    if (is64) return (int)((const long long*)ei)[idx];
    return ((const int*)ei)[idx];
}

__global__ void k_hist(const void* ei) {
    int e = blockIdx.x * blockDim.x + threadIdx.x;
    if (e < EE) {
        int d = load_edge(ei, (long long)EE + e, g_is64);
        atomicAdd(&g_count[d], 1);
    }
}

__global__ void k_scan1() {
    __shared__ int sh[1024];
    int i = blockIdx.x * 1024 + threadIdx.x;
    int v = (i < NN) ? g_count[i] : 0;
    sh[threadIdx.x] = v;
    __syncthreads();
    for (int off = 1; off < 1024; off <<= 1) {
        int t = (threadIdx.x >= off) ? sh[threadIdx.x - off] : 0;
        __syncthreads();
        sh[threadIdx.x] += t;
        __syncthreads();
    }
    if (i < NN) g_rowptr[i] = sh[threadIdx.x] - v;
    if (threadIdx.x == 1023) g_bsums[blockIdx.x] = sh[1023];
}

__global__ void k_scan23() {
    __shared__ int base;
    if (threadIdx.x == 0) {
        int run = 0;
        for (int b = 0; b < (int)blockIdx.x; b++) run += g_bsums[b];
        base = run;
    }
    __syncthreads();
    int i = blockIdx.x * 1024 + threadIdx.x;
    if (i < NN) {
        int r = g_rowptr[i] + base;
        g_rowptr[i] = r;
        g_cursor[i] = r;
        g_invdeg[i] = 1.0f / (float)max(g_count[i], 1);
    }
    if (i == 0) g_rowptr[NN] = EE;
}

__global__ void k_scatter(const void* ei) {
    int e = blockIdx.x * blockDim.x + threadIdx.x;
    if (e < EE) {
        int is64 = g_is64;
        int d = load_edge(ei, (long long)EE + e, is64);
        int s = load_edge(ei, e, is64);
        int p = atomicAdd(&g_cursor[d], 1);
        g_csrsrc[p] = s;
    }
}

// ---------------- mean aggregation: fp16 in -> fp16 plane out ----------------
template <int NV>
__global__ void k_agg_planes(const __half* __restrict__ X, __half* __restrict__ OF) {
    int w = (blockIdx.x * blockDim.x + threadIdx.x) >> 5;
    int lane = threadIdx.x & 31;
    if (w >= NN) return;
    int beg = g_rowptr[w], end = g_rowptr[w + 1];
    const int Wd = NV * 128;
    float4 acc[NV];
#pragma unroll
    for (int v = 0; v < NV; v++) acc[v] = make_float4(0.f, 0.f, 0.f, 0.f);
    int e = beg;
    for (; e + 4 <= end; e += 4) {
        int s0 = g_csrsrc[e], s1 = g_csrsrc[e + 1];
        int s2 = g_csrsrc[e + 2], s3 = g_csrsrc[e + 3];
        const uint2* r0 = (const uint2*)(X + (size_t)s0 * Wd);
        const uint2* r1 = (const uint2*)(X + (size_t)s1 * Wd);
        const uint2* r2 = (const uint2*)(X + (size_t)s2 * Wd);
        const uint2* r3 = (const uint2*)(X + (size_t)s3 * Wd);
#pragma unroll
        for (int v = 0; v < NV; v++) {
            uint2 u0 = r0[lane + 32 * v], u1 = r1[lane + 32 * v];
            uint2 u2 = r2[lane + 32 * v], u3 = r3[lane + 32 * v];
            float2 a0 = __half22float2(*(__half2*)&u0.x), b0 = __half22float2(*(__half2*)&u0.y);
            float2 a1 = __half22float2(*(__half2*)&u1.x), b1 = __half22float2(*(__half2*)&u1.y);
            float2 a2 = __half22float2(*(__half2*)&u2.x), b2 = __half22float2(*(__half2*)&u2.y);
            float2 a3 = __half22float2(*(__half2*)&u3.x), b3 = __half22float2(*(__half2*)&u3.y);
            acc[v].x += a0.x + a1.x + a2.x + a3.x;
            acc[v].y += a0.y + a1.y + a2.y + a3.y;
            acc[v].z += b0.x + b1.x + b2.x + b3.x;
            acc[v].w += b0.y + b1.y + b2.y + b3.y;
        }
    }
    for (; e < end; e++) {
        const uint2* r = (const uint2*)(X + (size_t)g_csrsrc[e] * Wd);
#pragma unroll
        for (int v = 0; v < NV; v++) {
            uint2 u = r[lane + 32 * v];
            float2 a = __half22float2(*(__half2*)&u.x), b = __half22float2(*(__half2*)&u.y);
            acc[v].x += a.x; acc[v].y += a.y; acc[v].z += b.x; acc[v].w += b.y;
        }
    }
    float inv = g_invdeg[w];
#pragma unroll
    for (int v = 0; v < NV; v++) {
        float4 a = acc[v];
        a.x *= inv; a.y *= inv; a.z *= inv; a.w *= inv;
        __half2 p0 = __floats2half2_rn(a.x, a.y);
        __half2 p1 = __floats2half2_rn(a.z, a.w);
        uint2 o;
        o.x = *(uint32_t*)&p0;
        o.y = *(uint32_t*)&p1;
        ((uint2*)(OF + (size_t)w * Wd))[lane + 32 * v] = o;
    }
}

// mean-agg over t2 (fp16, stride T2S) + tmp (fp32) -> out (stride 47)
__global__ void k_agg47_add(const __half* __restrict__ T2, const float* __restrict__ Tmp,
                            float* __restrict__ out) {
    int w = (blockIdx.x * blockDim.x + threadIdx.x) >> 5;
    int lane = threadIdx.x & 31;
    if (w >= NN) return;
    int beg = g_rowptr[w], end = g_rowptr[w + 1];
    float a0 = 0.f, a1 = 0.f;
    int e = beg;
    for (; e + 4 <= end; e += 4) {
        int s0 = g_csrsrc[e], s1 = g_csrsrc[e + 1];
        int s2 = g_csrsrc[e + 2], s3 = g_csrsrc[e + 3];
        const __half* r0 = T2 + (size_t)s0 * T2S;
        const __half* r1 = T2 + (size_t)s1 * T2S;
        const __half* r2 = T2 + (size_t)s2 * T2S;
        const __half* r3 = T2 + (size_t)s3 * T2S;
        a0 += __half2float(r0[lane]) + __half2float(r1[lane]) +
              __half2float(r2[lane]) + __half2float(r3[lane]);
        if (lane < OUT_F - 32)
            a1 += __half2float(r0[lane + 32]) + __half2float(r1[lane + 32]) +
                  __half2float(r2[lane + 32]) + __half2float(r3[lane + 32]);
    }
    for (; e < end; e++) {
        const __half* row = T2 + (size_t)g_csrsrc[e] * T2S;
        a0 += __half2float(row[lane]);
        if (lane < OUT_F - 32) a1 += __half2float(row[lane + 32]);
    }
    float inv = g_invdeg[w];
    const float* tr = Tmp + (size_t)w * T2S;
    float* orow = out + (size_t)w * OUT_F;
    orow[lane] = a0 * inv + tr[lane];
    if (lane < OUT_F - 32) orow[lane + 32] = a1 * inv + tr[lane + 32];
}

// ---------------- GEMM: fp16 A single-plane, fp16 B hi/lo, 2 passes ----------
__device__ __forceinline__ void mma16816(float* c, const uint32_t* a, const uint32_t* b) {
    asm volatile(
        "mma.sync.aligned.m16n8k16.row.col.f32.f16.f16.f32 "
        "{%0,%1,%2,%3}, {%4,%5,%6,%7}, {%8,%9}, {%0,%1,%2,%3};"
        : "+f"(c[0]), "+f"(c[1]), "+f"(c[2]), "+f"(c[3])
        : "r"(a[0]), "r"(a[1]), "r"(a[2]), "r"(a[3]), "r"(b[0]), "r"(b[1]));
}
__device__ __forceinline__ void cp16(uint32_t dst, const void* src) {
    asm volatile("cp.async.cg.shared.global [%0], [%1], 16;" :: "r"(dst), "l"(src));
}
__device__ __forceinline__ void cp_commit() {
    asm volatile("cp.async.commit_group;" ::: "memory");
}
template <int N> __device__ __forceinline__ void cp_wait() {
    asm volatile("cp.async.wait_group %0;" :: "n"(N) : "memory");
}
__device__ __forceinline__ uint32_t smem_u32(const void* p) {
    uint32_t a;
    asm("{ .reg .u64 t; cvta.to.shared.u64 t, %1; cvt.u32.u64 %0, t; }"
        : "=r"(a) : "l"(p));
    return a;
}

#define APL 10240                        // plane: 128 rows x 80B (64B payload)
#define STAGE (3 * APL)                  // A, Bh, Bl
#define GEMM_SMEM (2 * STAGE)            // 61440

template <bool DUAL, bool BIAS, bool RELU, bool WPLANES, bool WPRE, bool SPLIT2>
__global__ void __launch_bounds__(128, 2)
k_mma(const __half* __restrict__ A1, int ldA1, int K1,
      const __half* __restrict__ B1h, const __half* __restrict__ B1l, int ldB1,
      const __half* __restrict__ A2, int ldA2, int K2,
      const __half* __restrict__ B2h, const __half* __restrict__ B2l, int ldB2,
      const float* __restrict__ bias,
      __half* __restrict__ Ch, int ldC, float* __restrict__ Cpre,
      __half* __restrict__ Ct2, float* __restrict__ Caux, int M) {
    constexpr int ASTR = 40;             // fp16 units (80 B row stride)
    extern __shared__ __align__(16) char smem[];
    const uint32_t sbase = smem_u32(smem);

    const int tid  = threadIdx.x;
    const int wid  = tid >> 5;
    const int lane = tid & 31;
    const int wm   = wid >> 1;           // 2 warps along M (64 rows)
    const int wn   = wid & 1;            // 2 warps along N (64 cols)
    const int gid  = lane >> 2;
    const int tig  = lane & 3;

    const int rowBase = blockIdx.x * 128;
    const int colBlk  = blockIdx.y * 128;

    float acc[4][8][4];
#pragma unroll
    for (int mt = 0; mt < 4; mt++)
#pragma unroll
        for (int nt = 0; nt < 8; nt++)
#pragma unroll
            for (int j = 0; j < 4; j++) acc[mt][nt][j] = 0.f;

    const int NC1 = K1 / 32;
    const int NC  = DUAL ? NC1 + K2 / 32 : NC1;

    auto issue = [&](int c) {
        const uint32_t sb = sbase + (c & 1) * STAGE;
        const int seg = (DUAL && c >= NC1) ? 1 : 0;
        const int k0 = (c - (seg ? NC1 : 0)) * 32;
        const __half* A  = seg ? A2  : A1;
        const __half* Bh = seg ? B2h : B1h;
        const __half* Bl = seg ? B2l : B1l;
        const int ldA = seg ? ldA2 : ldA1;
        const int ldB = seg ? ldB2 : ldB1;
#pragma unroll
        for (int i = tid; i < 1536; i += 128) {
            int p = i >> 9, r = (i >> 2) & 127, ch = i & 3;
            const __half* g;
            if (p == 0) {
                int gr = min(rowBase + r, M - 1);
                g = A + (size_t)gr * ldA + k0 + ch * 8;
            } else {
                g = (p == 2 ? Bl : Bh) + (size_t)(colBlk + r) * ldB + k0 + ch * 8;
            }
            cp16(sb + p * APL + r * 80 + ch * 16, g);
        }
        cp_commit();
    };

    issue(0);
    for (int c = 0; c < NC; c++) {
        if (c + 1 < NC) { issue(c + 1); cp_wait<1>(); }
        else            { cp_wait<0>(); }
        __syncthreads();
        const char* S = smem + (c & 1) * STAGE;
        const __half* Af  = (const __half*)(S);
        const __half* Bhi = (const __half*)(S + APL);
        const __half* Blo = (const __half*)(S + 2 * APL);
#pragma unroll
        for (int ks = 0; ks < 2; ks++) {
            const int kb = ks * 16;
            uint32_t a[4][4];
#pragma unroll
            for (int mt = 0; mt < 4; mt++) {
                int r0 = 64 * wm + mt * 16 + gid;
                const uint32_t* ap  = (const uint32_t*)(Af + r0 * ASTR + kb);
                const uint32_t* ap8 = (const uint32_t*)(Af + (r0 + 8) * ASTR + kb);
                a[mt][0] = ap[tig];
                a[mt][1] = ap8[tig];
                a[mt][2] = ap[tig + 4];
                a[mt][3] = ap8[tig + 4];
            }
#pragma unroll
            for (int pv = 0; pv < 2; pv++) {
                const __half* Bs = pv ? Blo : Bhi;
                uint32_t b[8][2];
#pragma unroll
                for (int nt = 0; nt < 8; nt++) {
                    int br = 64 * wn + nt * 8 + gid;
                    const uint32_t* bp = (const uint32_t*)(Bs + br * ASTR + kb);
                    b[nt][0] = bp[tig];
                    b[nt][1] = bp[tig + 4];
                }
#pragma unroll
                for (int mt = 0; mt < 4; mt++)
#pragma unroll
                    for (int nt = 0; nt < 8; nt++)
                        mma16816(acc[mt][nt], a[mt], b[nt]);
            }
        }
        __syncthreads();
    }

    // ---- epilogue ----
#pragma unroll
    for (int mt = 0; mt < 4; mt++) {
        int r0 = rowBase + 64 * wm + mt * 16 + gid;
#pragma unroll
        for (int nt = 0; nt < 8; nt++) {
            int gc = colBlk + 64 * wn + nt * 8 + 2 * tig;
#pragma unroll
            for (int half = 0; half < 2; half++) {
                int rr = r0 + half * 8;
                if (rr >= M) continue;
                float v0 = acc[mt][nt][half * 2 + 0];
                float v1 = acc[mt][nt][half * 2 + 1];
                if (SPLIT2) {
#pragma unroll
                    for (int q = 0; q < 2; q++) {
                        int col = gc + q;
                        float v = q ? v1 : v0;
                        if (col < 64) {
                            if (col < OUT_F) Ct2[(size_t)rr * T2S + col] = __float2half_rn(v);
                        } else {
                            int c2 = col - 64;
                            if (c2 < OUT_F) Caux[(size_t)rr * T2S + c2] = v + bias[c2];
                        }
                    }
                } else {
                    if (BIAS) { v0 += bias[gc]; v1 += bias[gc + 1]; }
                    if (WPRE) {
                        float* p = Cpre + (size_t)rr * ldC + gc;
                        p[0] = v0; p[1] = v1;
                    }
                    if (RELU) { v0 = fmaxf(v0, 0.f); v1 = fmaxf(v1, 0.f); }
                    if (WPLANES) {
                        __half2 hp = __floats2half2_rn(v0, v1);
                        *(__half2*)(Ch + (size_t)rr * ldC + gc) = hp;
                    }
                }
            }
        }
    }
}

// ---------------- launch ----------------------------------------------------
extern "C" void kernel_launch(void* const* d_in, const int* in_sizes, int n_in,
                              void* d_out, int out_size) {
    const float* x   = (const float*)d_in[0];
    const void*  ei  = d_in[1];
    const float* Wl0 = (const float*)d_in[2];
    const float* bl0 = (const float*)d_in[3];
    const float* Wr0 = (const float*)d_in[4];
    const float* Wl1 = (const float*)d_in[5];
    const float* bl1 = (const float*)d_in[6];
    const float* Wr1 = (const float*)d_in[7];
    const float* Wl2 = (const float*)d_in[8];
    const float* bl2 = (const float*)d_in[9];
    const float* Wr2 = (const float*)d_in[10];

    float* out  = (float*)d_out;
    float* hout = out + (size_t)NN * OUT_F;

    float* p_tmp;
    __half *xf, *aggf, *hf, *h2f, *t2, *wfh, *wfl;
    cudaGetSymbolAddress((void**)&p_tmp, g_tmp);
    cudaGetSymbolAddress((void**)&xf,   g_xf);
    cudaGetSymbolAddress((void**)&aggf, g_aggf);
    cudaGetSymbolAddress((void**)&hf,   g_hf);
    cudaGetSymbolAddress((void**)&h2f,  g_h2f);
    cudaGetSymbolAddress((void**)&t2,   g_t2);
    cudaGetSymbolAddress((void**)&wfh,  g_wfh);
    cudaGetSymbolAddress((void**)&wfl,  g_wfl);

    cudaFuncSetAttribute(k_mma<true,  true, true,  true,  false, false>,
                         cudaFuncAttributeMaxDynamicSharedMemorySize, GEMM_SMEM);
    cudaFuncSetAttribute(k_mma<true,  true, true,  true,  true,  false>,
                         cudaFuncAttributeMaxDynamicSharedMemorySize, GEMM_SMEM);
    cudaFuncSetAttribute(k_mma<false, true, false, false, false, true>,
                         cudaFuncAttributeMaxDynamicSharedMemorySize, GEMM_SMEM);

    const int MT = (NN + 127) / 128;               // 782
    const int AGG_BLKS = (NN + 7) / 8;

    // prep + CSR build; x plane conversion before first aggregation
    k_prep<<<(WB_TOTAL + 255) / 256, 256>>>((const int*)ei, Wl0, Wr0, Wl1, Wr1, Wl2, Wr2);
    k_cvt<<<(NN * IN_F / 4 + 255) / 256, 256>>>((const float4*)x, (uint2*)xf, NN * IN_F / 4);
    k_hist<<<(EE + 255) / 256, 256>>>(ei);
    k_scan1<<<(NN + 1023) / 1024, 1024>>>();
    k_scan23<<<(NN + 1023) / 1024, 1024>>>();
    k_scatter<<<(EE + 255) / 256, 256>>>(ei);

    // layer 0: relu(agg(x)@Wl0 + bl0 + x@Wr0) -> hf plane
    k_agg_planes<1><<<AGG_BLKS, 256>>>(xf, aggf);
    k_mma<true, true, true, true, false, false><<<dim3(MT, 2), 128, GEMM_SMEM>>>(
        aggf, IN_F, IN_F, wfh + 0,     wfl + 0,     IN_F,
        xf,   IN_F, IN_F, wfh + 32768, wfl + 32768, IN_F,
        bl0, hf, HID_F, nullptr, nullptr, nullptr, NN);

    // layer 1: pre -> hout (fp32); relu -> h2f plane
    k_agg_planes<2><<<AGG_BLKS, 256>>>(hf, aggf);
    k_mma<true, true, true, true, true, false><<<dim3(MT, 2), 128, GEMM_SMEM>>>(
        aggf, HID_F, HID_F, wfh + 65536,  wfl + 65536,  HID_F,
        hf,   HID_F, HID_F, wfh + 131072, wfl + 131072, HID_F,
        bl1, h2f, HID_F, hout, nullptr, nullptr, NN);

    // layer 2 fused: t2 = h2@Wl2 (fp16) ; tmp = h2@Wr2 + bl2 (fp32)
    k_mma<false, true, false, false, false, true><<<dim3(MT, 1), 128, GEMM_SMEM>>>(
        h2f, HID_F, HID_F, wfh + 196608, wfl + 196608, HID_F,
        nullptr, 0, 0, nullptr, nullptr, 0,
        bl2, nullptr, T2S, nullptr, t2, p_tmp, NN);
    // out = mean-agg(t2) + tmp
    k_agg47_add<<<AGG_BLKS, 256>>>(t2, p_tmp, out);
}

// round 10
// speedup vs baseline: 2.0144x; 1.2549x over previous
#include <cuda_runtime.h>
#include <cuda_fp16.h>
#include <cstdint>

#define NN 100000
#define EE 1600000
#define IN_F 128
#define HID_F 256
#define OUT_F 47
#define T2S 48

// ---------------- scratch ---------------------------------------------------
__device__ float g_tmp[(size_t)NN * T2S];           // layer-2 direct term (fp32)
__device__ __align__(16) __half g_xf  [(size_t)NN * IN_F];
__device__ __align__(16) __half g_aggf[(size_t)NN * HID_F];
__device__ __align__(16) __half g_hf  [(size_t)NN * HID_F];
__device__ __align__(16) __half g_h2f [(size_t)NN * HID_F];
__device__ __align__(16) __half g_t2  [(size_t)NN * T2S];
__device__ int   g_count [NN];
__device__ float g_invdeg[NN];
__device__ int   g_rowptr[NN + 1];
__device__ int   g_cursor[NN];
__device__ int   g_csrsrc[EE];
__device__ int   g_bsums [128];
__device__ int   g_is64;

// weight table, fp16, transposed [N,K] row-major
// B0l 0 (256x128), B0r 32768, B1l 65536 (256x256), B1r 131072,
// B2 combined 196608 (128x256: rows 0-63 = Wl2, 64-127 = Wr2)
#define WB_TOTAL 229376
__device__ __align__(16) __half g_wf[WB_TOTAL];

// ---------------- prep ------------------------------------------------------
__global__ void k_prep(const int* ei_raw,
                       const float* Wl0, const float* Wr0,
                       const float* Wl1, const float* Wr1,
                       const float* Wl2, const float* Wr2) {
    int idx = blockIdx.x * blockDim.x + threadIdx.x;
    if (idx < NN) g_count[idx] = 0;
    if (idx == 0) {
        int is64 = 1;
        for (int i = 0; i < 256; i++)
            if (ei_raw[2 * i + 1] != 0) { is64 = 0; break; }
        g_is64 = is64;
    }
    if (idx < WB_TOTAL) {
        float w;
        if (idx < 32768)       { int l = idx;          int n = l >> 7, k = l & 127; w = Wl0[k * 256 + n]; }
        else if (idx < 65536)  { int l = idx - 32768;  int n = l >> 7, k = l & 127; w = Wr0[k * 256 + n]; }
        else if (idx < 131072) { int l = idx - 65536;  int n = l >> 8, k = l & 255; w = Wl1[k * 256 + n]; }
        else if (idx < 196608) { int l = idx - 131072; int n = l >> 8, k = l & 255; w = Wr1[k * 256 + n]; }
        else if (idx < 212992) { int l = idx - 196608; int n = l >> 8, k = l & 255; w = (n < OUT_F) ? Wl2[k * OUT_F + n] : 0.f; }
        else                   { int l = idx - 212992; int n = l >> 8, k = l & 255; w = (n < OUT_F) ? Wr2[k * OUT_F + n] : 0.f; }
        g_wf[idx] = __float2half_rn(w);
    }
}

// x fp32 -> fp16 plane
__global__ void k_cvt(const float4* __restrict__ X, uint2* __restrict__ O, int n4) {
    int i = blockIdx.x * blockDim.x + threadIdx.x;
    if (i >= n4) return;
    float4 v = X[i];
    __half2 p0 = __floats2half2_rn(v.x, v.y);
    __half2 p1 = __floats2half2_rn(v.z, v.w);
    uint2 o;
    o.x = *(uint32_t*)&p0;
    o.y = *(uint32_t*)&p1;
    O[i] = o;
}

// ---------------- CSR build -------------------------------------------------
__device__ __forceinline__ int load_edge(const void* ei, long long idx, int is64) {
    if (is64) return (int)((const long long*)ei)[idx];
    return ((const int*)ei)[idx];
}

__global__ void k_hist(const void* ei) {
    int e = blockIdx.x * blockDim.x + threadIdx.x;
    if (e < EE) {
        int d = load_edge(ei, (long long)EE + e, g_is64);
        atomicAdd(&g_count[d], 1);
    }
}

__global__ void k_scan1() {
    __shared__ int sh[1024];
    int i = blockIdx.x * 1024 + threadIdx.x;
    int v = (i < NN) ? g_count[i] : 0;
    sh[threadIdx.x] = v;
    __syncthreads();
    for (int off = 1; off < 1024; off <<= 1) {
        int t = (threadIdx.x >= off) ? sh[threadIdx.x - off] : 0;
        __syncthreads();
        sh[threadIdx.x] += t;
        __syncthreads();
    }
    if (i < NN) g_rowptr[i] = sh[threadIdx.x] - v;
    if (threadIdx.x == 1023) g_bsums[blockIdx.x] = sh[1023];
}

__global__ void k_scan23() {
    __shared__ int base;
    if (threadIdx.x == 0) {
        int run = 0;
        for (int b = 0; b < (int)blockIdx.x; b++) run += g_bsums[b];
        base = run;
    }
    __syncthreads();
    int i = blockIdx.x * 1024 + threadIdx.x;
    if (i < NN) {
        int r = g_rowptr[i] + base;
        g_rowptr[i] = r;
        g_cursor[i] = r;
        g_invdeg[i] = 1.0f / (float)max(g_count[i], 1);
    }
    if (i == 0) g_rowptr[NN] = EE;
}

__global__ void k_scatter(const void* ei) {
    int e = blockIdx.x * blockDim.x + threadIdx.x;
    if (e < EE) {
        int is64 = g_is64;
        int d = load_edge(ei, (long long)EE + e, is64);
        int s = load_edge(ei, e, is64);
        int p = atomicAdd(&g_cursor[d], 1);
        g_csrsrc[p] = s;
    }
}

// ---------------- mean aggregation: fp16 in -> fp16 plane out ----------------
template <int NV>
__global__ void k_agg_planes(const __half* __restrict__ X, __half* __restrict__ OF) {
    int w = (blockIdx.x * blockDim.x + threadIdx.x) >> 5;
    int lane = threadIdx.x & 31;
    if (w >= NN) return;
    int beg = g_rowptr[w], end = g_rowptr[w + 1];
    const int Wd = NV * 128;
    float4 acc[NV];
#pragma unroll
    for (int v = 0; v < NV; v++) acc[v] = make_float4(0.f, 0.f, 0.f, 0.f);
    int e = beg;
    for (; e + 4 <= end; e += 4) {
        int s0 = g_csrsrc[e], s1 = g_csrsrc[e + 1];
        int s2 = g_csrsrc[e + 2], s3 = g_csrsrc[e + 3];
        const uint2* r0 = (const uint2*)(X + (size_t)s0 * Wd);
        const uint2* r1 = (const uint2*)(X + (size_t)s1 * Wd);
        const uint2* r2 = (const uint2*)(X + (size_t)s2 * Wd);
        const uint2* r3 = (const uint2*)(X + (size_t)s3 * Wd);
#pragma unroll
        for (int v = 0; v < NV; v++) {
            uint2 u0 = r0[lane + 32 * v], u1 = r1[lane + 32 * v];
            uint2 u2 = r2[lane + 32 * v], u3 = r3[lane + 32 * v];
            float2 a0 = __half22float2(*(__half2*)&u0.x), b0 = __half22float2(*(__half2*)&u0.y);
            float2 a1 = __half22float2(*(__half2*)&u1.x), b1 = __half22float2(*(__half2*)&u1.y);
            float2 a2 = __half22float2(*(__half2*)&u2.x), b2 = __half22float2(*(__half2*)&u2.y);
            float2 a3 = __half22float2(*(__half2*)&u3.x), b3 = __half22float2(*(__half2*)&u3.y);
            acc[v].x += a0.x + a1.x + a2.x + a3.x;
            acc[v].y += a0.y + a1.y + a2.y + a3.y;
            acc[v].z += b0.x + b1.x + b2.x + b3.x;
            acc[v].w += b0.y + b1.y + b2.y + b3.y;
        }
    }
    for (; e < end; e++) {
        const uint2* r = (const uint2*)(X + (size_t)g_csrsrc[e] * Wd);
#pragma unroll
        for (int v = 0; v < NV; v++) {
            uint2 u = r[lane + 32 * v];
            float2 a = __half22float2(*(__half2*)&u.x), b = __half22float2(*(__half2*)&u.y);
            acc[v].x += a.x; acc[v].y += a.y; acc[v].z += b.x; acc[v].w += b.y;
        }
    }
    float inv = g_invdeg[w];
#pragma unroll
    for (int v = 0; v < NV; v++) {
        float4 a = acc[v];
        a.x *= inv; a.y *= inv; a.z *= inv; a.w *= inv;
        __half2 p0 = __floats2half2_rn(a.x, a.y);
        __half2 p1 = __floats2half2_rn(a.z, a.w);
        uint2 o;
        o.x = *(uint32_t*)&p0;
        o.y = *(uint32_t*)&p1;
        ((uint2*)(OF + (size_t)w * Wd))[lane + 32 * v] = o;
    }
}

// mean-agg over t2 (fp16, stride T2S) + tmp (fp32) -> out (stride 47)
__global__ void k_agg47_add(const __half* __restrict__ T2, const float* __restrict__ Tmp,
                            float* __restrict__ out) {
    int w = (blockIdx.x * blockDim.x + threadIdx.x) >> 5;
    int lane = threadIdx.x & 31;
    if (w >= NN) return;
    int beg = g_rowptr[w], end = g_rowptr[w + 1];
    float a0 = 0.f, a1 = 0.f;
    int e = beg;
    for (; e + 4 <= end; e += 4) {
        int s0 = g_csrsrc[e], s1 = g_csrsrc[e + 1];
        int s2 = g_csrsrc[e + 2], s3 = g_csrsrc[e + 3];
        const __half* r0 = T2 + (size_t)s0 * T2S;
        const __half* r1 = T2 + (size_t)s1 * T2S;
        const __half* r2 = T2 + (size_t)s2 * T2S;
        const __half* r3 = T2 + (size_t)s3 * T2S;
        a0 += __half2float(r0[lane]) + __half2float(r1[lane]) +
              __half2float(r2[lane]) + __half2float(r3[lane]);
        if (lane < OUT_F - 32)
            a1 += __half2float(r0[lane + 32]) + __half2float(r1[lane + 32]) +
                  __half2float(r2[lane + 32]) + __half2float(r3[lane + 32]);
    }
    for (; e < end; e++) {
        const __half* row = T2 + (size_t)g_csrsrc[e] * T2S;
        a0 += __half2float(row[lane]);
        if (lane < OUT_F - 32) a1 += __half2float(row[lane + 32]);
    }
    float inv = g_invdeg[w];
    const float* tr = Tmp + (size_t)w * T2S;
    float* orow = out + (size_t)w * OUT_F;
    orow[lane] = a0 * inv + tr[lane];
    if (lane < OUT_F - 32) orow[lane + 32] = a1 * inv + tr[lane + 32];
}

// ---------------- GEMM: fp16 A + fp16 B, single pass -------------------------
__device__ __forceinline__ void mma16816(float* c, const uint32_t* a, const uint32_t* b) {
    asm volatile(
        "mma.sync.aligned.m16n8k16.row.col.f32.f16.f16.f32 "
        "{%0,%1,%2,%3}, {%4,%5,%6,%7}, {%8,%9}, {%0,%1,%2,%3};"
        : "+f"(c[0]), "+f"(c[1]), "+f"(c[2]), "+f"(c[3])
        : "r"(a[0]), "r"(a[1]), "r"(a[2]), "r"(a[3]), "r"(b[0]), "r"(b[1]));
}
__device__ __forceinline__ void cp16(uint32_t dst, const void* src) {
    asm volatile("cp.async.cg.shared.global [%0], [%1], 16;" :: "r"(dst), "l"(src));
}
__device__ __forceinline__ void cp_commit() {
    asm volatile("cp.async.commit_group;" ::: "memory");
}
template <int N> __device__ __forceinline__ void cp_wait() {
    asm volatile("cp.async.wait_group %0;" :: "n"(N) : "memory");
}
__device__ __forceinline__ uint32_t smem_u32(const void* p) {
    uint32_t a;
    asm("{ .reg .u64 t; cvta.to.shared.u64 t, %1; cvt.u32.u64 %0, t; }"
        : "=r"(a) : "l"(p));
    return a;
}

#define APL 10240                        // plane: 128 rows x 80B (64B payload)
#define STAGE (2 * APL)                  // A, B
#define GEMM_SMEM (2 * STAGE)            // 40960

template <bool DUAL, bool BIAS, bool RELU, bool WPLANES, bool WPRE, bool SPLIT2>
__global__ void __launch_bounds__(128, 2)
k_mma(const __half* __restrict__ A1, int ldA1, int K1,
      const __half* __restrict__ B1, int ldB1,
      const __half* __restrict__ A2, int ldA2, int K2,
      const __half* __restrict__ B2, int ldB2,
      const float* __restrict__ bias,
      __half* __restrict__ Ch, int ldC, float* __restrict__ Cpre,
      __half* __restrict__ Ct2, float* __restrict__ Caux, int M) {
    constexpr int ASTR = 40;             // fp16 units (80 B row stride)
    extern __shared__ __align__(16) char smem[];
    const uint32_t sbase = smem_u32(smem);

    const int tid  = threadIdx.x;
    const int wid  = tid >> 5;
    const int lane = tid & 31;
    const int wm   = wid >> 1;           // 2 warps along M (64 rows)
    const int wn   = wid & 1;            // 2 warps along N (64 cols)
    const int gid  = lane >> 2;
    const int tig  = lane & 3;

    const int rowBase = blockIdx.x * 128;
    const int colBlk  = blockIdx.y * 128;

    float acc[4][8][4];
#pragma unroll
    for (int mt = 0; mt < 4; mt++)
#pragma unroll
        for (int nt = 0; nt < 8; nt++)
#pragma unroll
            for (int j = 0; j < 4; j++) acc[mt][nt][j] = 0.f;

    const int NC1 = K1 / 32;
    const int NC  = DUAL ? NC1 + K2 / 32 : NC1;

    auto issue = [&](int c) {
        const uint32_t sb = sbase + (c & 1) * STAGE;
        const int seg = (DUAL && c >= NC1) ? 1 : 0;
        const int k0 = (c - (seg ? NC1 : 0)) * 32;
        const __half* A = seg ? A2 : A1;
        const __half* B = seg ? B2 : B1;
        const int ldA = seg ? ldA2 : ldA1;
        const int ldB = seg ? ldB2 : ldB1;
#pragma unroll
        for (int i = tid; i < 1024; i += 128) {
            int p = i >> 9, r = (i >> 2) & 127, ch = i & 3;
            const __half* g;
            if (p == 0) {
                int gr = min(rowBase + r, M - 1);
                g = A + (size_t)gr * ldA + k0 + ch * 8;
            } else {
                g = B + (size_t)(colBlk + r) * ldB + k0 + ch * 8;
            }
            cp16(sb + p * APL + r * 80 + ch * 16, g);
        }
        cp_commit();
    };

    issue(0);
    for (int c = 0; c < NC; c++) {
        if (c + 1 < NC) { issue(c + 1); cp_wait<1>(); }
        else            { cp_wait<0>(); }
        __syncthreads();
        const char* S = smem + (c & 1) * STAGE;
        const __half* Af = (const __half*)(S);
        const __half* Bf = (const __half*)(S + APL);
#pragma unroll
        for (int ks = 0; ks < 2; ks++) {
            const int kb = ks * 16;
            uint32_t a[4][4];
#pragma unroll
            for (int mt = 0; mt < 4; mt++) {
                int r0 = 64 * wm + mt * 16 + gid;
                const uint32_t* ap  = (const uint32_t*)(Af + r0 * ASTR + kb);
                const uint32_t* ap8 = (const uint32_t*)(Af + (r0 + 8) * ASTR + kb);
                a[mt][0] = ap[tig];
                a[mt][1] = ap8[tig];
                a[mt][2] = ap[tig + 4];
                a[mt][3] = ap8[tig + 4];
            }
            uint32_t b[8][2];
#pragma unroll
            for (int nt = 0; nt < 8; nt++) {
                int br = 64 * wn + nt * 8 + gid;
                const uint32_t* bp = (const uint32_t*)(Bf + br * ASTR + kb);
                b[nt][0] = bp[tig];
                b[nt][1] = bp[tig + 4];
            }
#pragma unroll
            for (int mt = 0; mt < 4; mt++)
#pragma unroll
                for (int nt = 0; nt < 8; nt++)
                    mma16816(acc[mt][nt], a[mt], b[nt]);
        }
        __syncthreads();
    }

    // ---- epilogue ----
#pragma unroll
    for (int mt = 0; mt < 4; mt++) {
        int r0 = rowBase + 64 * wm + mt * 16 + gid;
#pragma unroll
        for (int nt = 0; nt < 8; nt++) {
            int gc = colBlk + 64 * wn + nt * 8 + 2 * tig;
#pragma unroll
            for (int half = 0; half < 2; half++) {
                int rr = r0 + half * 8;
                if (rr >= M) continue;
                float v0 = acc[mt][nt][half * 2 + 0];
                float v1 = acc[mt][nt][half * 2 + 1];
                if (SPLIT2) {
#pragma unroll
                    for (int q = 0; q < 2; q++) {
                        int col = gc + q;
                        float v = q ? v1 : v0;
                        if (col < 64) {
                            if (col < OUT_F) Ct2[(size_t)rr * T2S + col] = __float2half_rn(v);
                        } else {
                            int c2 = col - 64;
                            if (c2 < OUT_F) Caux[(size_t)rr * T2S + c2] = v + bias[c2];
                        }
                    }
                } else {
                    if (BIAS) { v0 += bias[gc]; v1 += bias[gc + 1]; }
                    if (WPRE) {
                        float* p = Cpre + (size_t)rr * ldC + gc;
                        p[0] = v0; p[1] = v1;
                    }
                    if (RELU) { v0 = fmaxf(v0, 0.f); v1 = fmaxf(v1, 0.f); }
                    if (WPLANES) {
                        __half2 hp = __floats2half2_rn(v0, v1);
                        *(__half2*)(Ch + (size_t)rr * ldC + gc) = hp;
                    }
                }
            }
        }
    }
}

// ---------------- launch ----------------------------------------------------
extern "C" void kernel_launch(void* const* d_in, const int* in_sizes, int n_in,
                              void* d_out, int out_size) {
    const float* x   = (const float*)d_in[0];
    const void*  ei  = d_in[1];
    const float* Wl0 = (const float*)d_in[2];
    const float* bl0 = (const float*)d_in[3];
    const float* Wr0 = (const float*)d_in[4];
    const float* Wl1 = (const float*)d_in[5];
    const float* bl1 = (const float*)d_in[6];
    const float* Wr1 = (const float*)d_in[7];
    const float* Wl2 = (const float*)d_in[8];
    const float* bl2 = (const float*)d_in[9];
    const float* Wr2 = (const float*)d_in[10];

    float* out  = (float*)d_out;
    float* hout = out + (size_t)NN * OUT_F;

    float* p_tmp;
    __half *xf, *aggf, *hf, *h2f, *t2, *wf;
    cudaGetSymbolAddress((void**)&p_tmp, g_tmp);
    cudaGetSymbolAddress((void**)&xf,   g_xf);
    cudaGetSymbolAddress((void**)&aggf, g_aggf);
    cudaGetSymbolAddress((void**)&hf,   g_hf);
    cudaGetSymbolAddress((void**)&h2f,  g_h2f);
    cudaGetSymbolAddress((void**)&t2,   g_t2);
    cudaGetSymbolAddress((void**)&wf,   g_wf);

    cudaFuncSetAttribute(k_mma<true,  true, true,  true,  false, false>,
                         cudaFuncAttributeMaxDynamicSharedMemorySize, GEMM_SMEM);
    cudaFuncSetAttribute(k_mma<true,  true, true,  true,  true,  false>,
                         cudaFuncAttributeMaxDynamicSharedMemorySize, GEMM_SMEM);
    cudaFuncSetAttribute(k_mma<false, true, false, false, false, true>,
                         cudaFuncAttributeMaxDynamicSharedMemorySize, GEMM_SMEM);

    const int MT = (NN + 127) / 128;               // 782
    const int AGG_BLKS = (NN + 7) / 8;

    // prep + CSR build; x plane conversion before first aggregation
    k_prep<<<(WB_TOTAL + 255) / 256, 256>>>((const int*)ei, Wl0, Wr0, Wl1, Wr1, Wl2, Wr2);
    k_cvt<<<(NN * IN_F / 4 + 255) / 256, 256>>>((const float4*)x, (uint2*)xf, NN * IN_F / 4);
    k_hist<<<(EE + 255) / 256, 256>>>(ei);
    k_scan1<<<(NN + 1023) / 1024, 1024>>>();
    k_scan23<<<(NN + 1023) / 1024, 1024>>>();
    k_scatter<<<(EE + 255) / 256, 256>>>(ei);

    // layer 0: relu(agg(x)@Wl0 + bl0 + x@Wr0) -> hf plane
    k_agg_planes<1><<<AGG_BLKS, 256>>>(xf, aggf);
    k_mma<true, true, true, true, false, false><<<dim3(MT, 2), 128, GEMM_SMEM>>>(
        aggf, IN_F, IN_F, wf + 0,     IN_F,
        xf,   IN_F, IN_F, wf + 32768, IN_F,
        bl0, hf, HID_F, nullptr, nullptr, nullptr, NN);

    // layer 1: pre -> hout (fp32); relu -> h2f plane
    k_agg_planes<2><<<AGG_BLKS, 256>>>(hf, aggf);
    k_mma<true, true, true, true, true, false><<<dim3(MT, 2), 128, GEMM_SMEM>>>(
        aggf, HID_F, HID_F, wf + 65536,  HID_F,
        hf,   HID_F, HID_F, wf + 131072, HID_F,
        bl1, h2f, HID_F, hout, nullptr, nullptr, NN);

    // layer 2 fused: t2 = h2@Wl2 (fp16) ; tmp = h2@Wr2 + bl2 (fp32)
    k_mma<false, true, false, false, false, true><<<dim3(MT, 1), 128, GEMM_SMEM>>>(
        h2f, HID_F, HID_F, wf + 196608, HID_F,
        nullptr, 0, 0, nullptr, 0,
        bl2, nullptr, T2S, nullptr, t2, p_tmp, NN);
    // out = mean-agg(t2) + tmp
    k_agg47_add<<<AGG_BLKS, 256>>>(t2, p_tmp, out);
}

// round 11
// speedup vs baseline: 2.0601x; 1.0227x over previous
#include <cuda_runtime.h>
#include <cuda_fp16.h>
#include <cstdint>

#define NN 100000
#define EE 1600000
#define IN_F 128
#define HID_F 256
#define OUT_F 47
#define T2S 48

// ---------------- scratch ---------------------------------------------------
__device__ float g_tmp[(size_t)NN * T2S];           // layer-2 direct term (fp32)
__device__ __align__(16) __half g_xf  [(size_t)NN * IN_F];
__device__ __align__(16) __half g_aggf[(size_t)NN * HID_F];
__device__ __align__(16) __half g_hf  [(size_t)NN * HID_F];
__device__ __align__(16) __half g_h2f [(size_t)NN * HID_F];
__device__ __align__(16) __half g_t2  [(size_t)NN * T2S];
__device__ int   g_count [NN];
__device__ float g_invdeg[NN];
__device__ int   g_rowptr[NN + 1];
__device__ int   g_cursor[NN];
__device__ int   g_csrsrc[EE];
__device__ int   g_bsums [128];
__device__ int   g_is64;

// weight table, fp16, transposed [N,K] row-major
#define WB_TOTAL 229376
__device__ __align__(16) __half g_wf[WB_TOTAL];

// ---------------- prep ------------------------------------------------------
__global__ void k_prep(const int* ei_raw,
                       const float* Wl0, const float* Wr0,
                       const float* Wl1, const float* Wr1,
                       const float* Wl2, const float* Wr2) {
    int idx = blockIdx.x * blockDim.x + threadIdx.x;
    if (idx < NN) g_count[idx] = 0;
    if (idx == 0) {
        int is64 = 1;
        for (int i = 0; i < 256; i++)
            if (ei_raw[2 * i + 1] != 0) { is64 = 0; break; }
        g_is64 = is64;
    }
    if (idx < WB_TOTAL) {
        float w;
        if (idx < 32768)       { int l = idx;          int n = l >> 7, k = l & 127; w = Wl0[k * 256 + n]; }
        else if (idx < 65536)  { int l = idx - 32768;  int n = l >> 7, k = l & 127; w = Wr0[k * 256 + n]; }
        else if (idx < 131072) { int l = idx - 65536;  int n = l >> 8, k = l & 255; w = Wl1[k * 256 + n]; }
        else if (idx < 196608) { int l = idx - 131072; int n = l >> 8, k = l & 255; w = Wr1[k * 256 + n]; }
        else if (idx < 212992) { int l = idx - 196608; int n = l >> 8, k = l & 255; w = (n < OUT_F) ? Wl2[k * OUT_F + n] : 0.f; }
        else                   { int l = idx - 212992; int n = l >> 8, k = l & 255; w = (n < OUT_F) ? Wr2[k * OUT_F + n] : 0.f; }
        g_wf[idx] = __float2half_rn(w);
    }
}

// x fp32 -> fp16 plane
__global__ void k_cvt(const float4* __restrict__ X, uint2* __restrict__ O, int n4) {
    int i = blockIdx.x * blockDim.x + threadIdx.x;
    if (i >= n4) return;
    float4 v = X[i];
    __half2 p0 = __floats2half2_rn(v.x, v.y);
    __half2 p1 = __floats2half2_rn(v.z, v.w);
    uint2 o;
    o.x = *(uint32_t*)&p0;
    o.y = *(uint32_t*)&p1;
    O[i] = o;
}

// ---------------- CSR build -------------------------------------------------
__device__ __forceinline__ int load_edge(const void* ei, long long idx, int is64) {
    if (is64) return (int)((const long long*)ei)[idx];
    return ((const int*)ei)[idx];
}

__global__ void k_hist(const void* ei) {
    int e = blockIdx.x * blockDim.x + threadIdx.x;
    if (e < EE) {
        int d = load_edge(ei, (long long)EE + e, g_is64);
        atomicAdd(&g_count[d], 1);
    }
}

__global__ void k_scan1() {
    __shared__ int sh[1024];
    int i = blockIdx.x * 1024 + threadIdx.x;
    int v = (i < NN) ? g_count[i] : 0;
    sh[threadIdx.x] = v;
    __syncthreads();
    for (int off = 1; off < 1024; off <<= 1) {
        int t = (threadIdx.x >= off) ? sh[threadIdx.x - off] : 0;
        __syncthreads();
        sh[threadIdx.x] += t;
        __syncthreads();
    }
    if (i < NN) g_rowptr[i] = sh[threadIdx.x] - v;
    if (threadIdx.x == 1023) g_bsums[blockIdx.x] = sh[1023];
}

__global__ void k_scan23() {
    __shared__ int base;
    if (threadIdx.x == 0) {
        int run = 0;
        for (int b = 0; b < (int)blockIdx.x; b++) run += g_bsums[b];
        base = run;
    }
    __syncthreads();
    int i = blockIdx.x * 1024 + threadIdx.x;
    if (i < NN) {
        int r = g_rowptr[i] + base;
        g_rowptr[i] = r;
        g_cursor[i] = r;
        g_invdeg[i] = 1.0f / (float)max(g_count[i], 1);
    }
    if (i == 0) g_rowptr[NN] = EE;
}

__global__ void k_scatter(const void* ei) {
    int e = blockIdx.x * blockDim.x + threadIdx.x;
    if (e < EE) {
        int is64 = g_is64;
        int d = load_edge(ei, (long long)EE + e, is64);
        int s = load_edge(ei, e, is64);
        int p = atomicAdd(&g_cursor[d], 1);
        g_csrsrc[p] = s;
    }
}

// ---------------- mean aggregation: fp16 -> fp16 plane ------------------------
// width 128: one uint2 (4 halfs) per lane per row
__global__ void k_agg128(const __half* __restrict__ X, __half* __restrict__ OF) {
    int w = (blockIdx.x * blockDim.x + threadIdx.x) >> 5;
    int lane = threadIdx.x & 31;
    if (w >= NN) return;
    int beg = g_rowptr[w], end = g_rowptr[w + 1];
    float4 acc = make_float4(0.f, 0.f, 0.f, 0.f);
    int e = beg;
    for (; e + 4 <= end; e += 4) {
        int s0 = g_csrsrc[e], s1 = g_csrsrc[e + 1];
        int s2 = g_csrsrc[e + 2], s3 = g_csrsrc[e + 3];
        uint2 u0 = ((const uint2*)(X + (size_t)s0 * IN_F))[lane];
        uint2 u1 = ((const uint2*)(X + (size_t)s1 * IN_F))[lane];
        uint2 u2 = ((const uint2*)(X + (size_t)s2 * IN_F))[lane];
        uint2 u3 = ((const uint2*)(X + (size_t)s3 * IN_F))[lane];
        float2 a0 = __half22float2(*(__half2*)&u0.x), b0 = __half22float2(*(__half2*)&u0.y);
        float2 a1 = __half22float2(*(__half2*)&u1.x), b1 = __half22float2(*(__half2*)&u1.y);
        float2 a2 = __half22float2(*(__half2*)&u2.x), b2 = __half22float2(*(__half2*)&u2.y);
        float2 a3 = __half22float2(*(__half2*)&u3.x), b3 = __half22float2(*(__half2*)&u3.y);
        acc.x += a0.x + a1.x + a2.x + a3.x;
        acc.y += a0.y + a1.y + a2.y + a3.y;
        acc.z += b0.x + b1.x + b2.x + b3.x;
        acc.w += b0.y + b1.y + b2.y + b3.y;
    }
    for (; e < end; e++) {
        uint2 u = ((const uint2*)(X + (size_t)g_csrsrc[e] * IN_F))[lane];
        float2 a = __half22float2(*(__half2*)&u.x), b = __half22float2(*(__half2*)&u.y);
        acc.x += a.x; acc.y += a.y; acc.z += b.x; acc.w += b.y;
    }
    float inv = g_invdeg[w];
    acc.x *= inv; acc.y *= inv; acc.z *= inv; acc.w *= inv;
    __half2 p0 = __floats2half2_rn(acc.x, acc.y);
    __half2 p1 = __floats2half2_rn(acc.z, acc.w);
    uint2 o;
    o.x = *(uint32_t*)&p0;
    o.y = *(uint32_t*)&p1;
    ((uint2*)(OF + (size_t)w * IN_F))[lane] = o;
}

// width 256: one uint4 (8 halfs) per lane per row
__global__ void k_agg256(const __half* __restrict__ X, __half* __restrict__ OF) {
    int w = (blockIdx.x * blockDim.x + threadIdx.x) >> 5;
    int lane = threadIdx.x & 31;
    if (w >= NN) return;
    int beg = g_rowptr[w], end = g_rowptr[w + 1];
    float acc[8];
#pragma unroll
    for (int j = 0; j < 8; j++) acc[j] = 0.f;
    int e = beg;
    for (; e + 4 <= end; e += 4) {
        int s0 = g_csrsrc[e], s1 = g_csrsrc[e + 1];
        int s2 = g_csrsrc[e + 2], s3 = g_csrsrc[e + 3];
        uint4 u0 = ((const uint4*)(X + (size_t)s0 * HID_F))[lane];
        uint4 u1 = ((const uint4*)(X + (size_t)s1 * HID_F))[lane];
        uint4 u2 = ((const uint4*)(X + (size_t)s2 * HID_F))[lane];
        uint4 u3 = ((const uint4*)(X + (size_t)s3 * HID_F))[lane];
#pragma unroll
        for (int q = 0; q < 4; q++) {
            uint32_t w0 = (&u0.x)[q], w1 = (&u1.x)[q], w2 = (&u2.x)[q], w3 = (&u3.x)[q];
            float2 f0 = __half22float2(*(__half2*)&w0);
            float2 f1 = __half22float2(*(__half2*)&w1);
            float2 f2 = __half22float2(*(__half2*)&w2);
            float2 f3 = __half22float2(*(__half2*)&w3);
            acc[2 * q]     += f0.x + f1.x + f2.x + f3.x;
            acc[2 * q + 1] += f0.y + f1.y + f2.y + f3.y;
        }
    }
    for (; e < end; e++) {
        uint4 u = ((const uint4*)(X + (size_t)g_csrsrc[e] * HID_F))[lane];
#pragma unroll
        for (int q = 0; q < 4; q++) {
            uint32_t ww = (&u.x)[q];
            float2 f = __half22float2(*(__half2*)&ww);
            acc[2 * q] += f.x; acc[2 * q + 1] += f.y;
        }
    }
    float inv = g_invdeg[w];
    uint4 o;
#pragma unroll
    for (int q = 0; q < 4; q++) {
        __half2 p = __floats2half2_rn(acc[2 * q] * inv, acc[2 * q + 1] * inv);
        (&o.x)[q] = *(uint32_t*)&p;
    }
    ((uint4*)(OF + (size_t)w * HID_F))[lane] = o;
}

// mean-agg over t2 (fp16, stride T2S) + tmp (fp32) -> out (stride 47)
// lanes 0..23: one 32-bit load (2 halfs) per row; lane 23's 2nd col discarded
__global__ void k_agg47_add(const __half* __restrict__ T2, const float* __restrict__ Tmp,
                            float* __restrict__ out) {
    int w = (blockIdx.x * blockDim.x + threadIdx.x) >> 5;
    int lane = threadIdx.x & 31;
    if (w >= NN || lane >= 24) return;
    int beg = g_rowptr[w], end = g_rowptr[w + 1];
    float a0 = 0.f, a1 = 0.f;
    int e = beg;
    for (; e + 4 <= end; e += 4) {
        int s0 = g_csrsrc[e], s1 = g_csrsrc[e + 1];
        int s2 = g_csrsrc[e + 2], s3 = g_csrsrc[e + 3];
        uint32_t u0 = *(const uint32_t*)(T2 + (size_t)s0 * T2S + lane * 2);
        uint32_t u1 = *(const uint32_t*)(T2 + (size_t)s1 * T2S + lane * 2);
        uint32_t u2 = *(const uint32_t*)(T2 + (size_t)s2 * T2S + lane * 2);
        uint32_t u3 = *(const uint32_t*)(T2 + (size_t)s3 * T2S + lane * 2);
        float2 f0 = __half22float2(*(__half2*)&u0);
        float2 f1 = __half22float2(*(__half2*)&u1);
        float2 f2 = __half22float2(*(__half2*)&u2);
        float2 f3 = __half22float2(*(__half2*)&u3);
        a0 += f0.x + f1.x + f2.x + f3.x;
        a1 += f0.y + f1.y + f2.y + f3.y;
    }
    for (; e < end; e++) {
        uint32_t u = *(const uint32_t*)(T2 + (size_t)g_csrsrc[e] * T2S + lane * 2);
        float2 f = __half22float2(*(__half2*)&u);
        a0 += f.x; a1 += f.y;
    }
    float inv = g_invdeg[w];
    const float* tr = Tmp + (size_t)w * T2S;
    float* orow = out + (size_t)w * OUT_F;
    int c0 = lane * 2, c1 = c0 + 1;
    orow[c0] = a0 * inv + tr[c0];
    if (c1 < OUT_F) orow[c1] = a1 * inv + tr[c1];
}

// ---------------- GEMM: fp16 A + fp16 B, 3-stage cp.async pipeline -----------
__device__ __forceinline__ void mma16816(float* c, const uint32_t* a, const uint32_t* b) {
    asm volatile(
        "mma.sync.aligned.m16n8k16.row.col.f32.f16.f16.f32 "
        "{%0,%1,%2,%3}, {%4,%5,%6,%7}, {%8,%9}, {%0,%1,%2,%3};"
        : "+f"(c[0]), "+f"(c[1]), "+f"(c[2]), "+f"(c[3])
        : "r"(a[0]), "r"(a[1]), "r"(a[2]), "r"(a[3]), "r"(b[0]), "r"(b[1]));
}
__device__ __forceinline__ void cp16(uint32_t dst, const void* src) {
    asm volatile("cp.async.cg.shared.global [%0], [%1], 16;" :: "r"(dst), "l"(src));
}
__device__ __forceinline__ void cp_commit() {
    asm volatile("cp.async.commit_group;" ::: "memory");
}
template <int N> __device__ __forceinline__ void cp_wait() {
    asm volatile("cp.async.wait_group %0;" :: "n"(N) : "memory");
}
__device__ __forceinline__ uint32_t smem_u32(const void* p) {
    uint32_t a;
    asm("{ .reg .u64 t; cvta.to.shared.u64 t, %1; cvt.u32.u64 %0, t; }"
        : "=r"(a) : "l"(p));
    return a;
}

#define APL 10240                        // plane: 128 rows x 80B (64B payload)
#define STAGE (2 * APL)                  // A, B
#define GEMM_SMEM (3 * STAGE)            // 61440

template <bool DUAL, bool BIAS, bool RELU, bool WPLANES, bool WPRE, bool SPLIT2>
__global__ void __launch_bounds__(128, 2)
k_mma(const __half* __restrict__ A1, int ldA1, int K1,
      const __half* __restrict__ B1, int ldB1,
      const __half* __restrict__ A2, int ldA2, int K2,
      const __half* __restrict__ B2, int ldB2,
      const float* __restrict__ bias,
      __half* __restrict__ Ch, int ldC, float* __restrict__ Cpre,
      __half* __restrict__ Ct2, float* __restrict__ Caux, int M) {
    constexpr int ASTR = 40;             // fp16 units (80 B row stride)
    extern __shared__ __align__(16) char smem[];
    const uint32_t sbase = smem_u32(smem);

    const int tid  = threadIdx.x;
    const int wid  = tid >> 5;
    const int lane = tid & 31;
    const int wm   = wid >> 1;           // 2 warps along M (64 rows)
    const int wn   = wid & 1;            // 2 warps along N (64 cols)
    const int gid  = lane >> 2;
    const int tig  = lane & 3;

    const int rowBase = blockIdx.x * 128;
    const int colBlk  = blockIdx.y * 128;

    float acc[4][8][4];
#pragma unroll
    for (int mt = 0; mt < 4; mt++)
#pragma unroll
        for (int nt = 0; nt < 8; nt++)
#pragma unroll
            for (int j = 0; j < 4; j++) acc[mt][nt][j] = 0.f;

    const int NC1 = K1 / 32;
    const int NC  = DUAL ? NC1 + K2 / 32 : NC1;

    auto issue = [&](int c) {
        const uint32_t sb = sbase + (c % 3) * STAGE;
        const int seg = (DUAL && c >= NC1) ? 1 : 0;
        const int k0 = (c - (seg ? NC1 : 0)) * 32;
        const __half* A = seg ? A2 : A1;
        const __half* B = seg ? B2 : B1;
        const int ldA = seg ? ldA2 : ldA1;
        const int ldB = seg ? ldB2 : ldB1;
#pragma unroll
        for (int i = tid; i < 1024; i += 128) {
            int p = i >> 9, r = (i >> 2) & 127, ch = i & 3;
            const __half* g;
            if (p == 0) {
                int gr = min(rowBase + r, M - 1);
                g = A + (size_t)gr * ldA + k0 + ch * 8;
            } else {
                g = B + (size_t)(colBlk + r) * ldB + k0 + ch * 8;
            }
            cp16(sb + p * APL + r * 80 + ch * 16, g);
        }
        cp_commit();
    };

    issue(0);
    issue(1);                            // NC >= 8 always
    for (int c = 0; c < NC; c++) {
        if (c + 2 < NC)      { issue(c + 2); cp_wait<2>(); }
        else if (c + 1 < NC) { cp_wait<1>(); }
        else                 { cp_wait<0>(); }
        __syncthreads();
        const char* S = smem + (c % 3) * STAGE;
        const __half* Af = (const __half*)(S);
        const __half* Bf = (const __half*)(S + APL);
#pragma unroll
        for (int ks = 0; ks < 2; ks++) {
            const int kb = ks * 16;
            uint32_t a[4][4];
#pragma unroll
            for (int mt = 0; mt < 4; mt++) {
                int r0 = 64 * wm + mt * 16 + gid;
                const uint32_t* ap  = (const uint32_t*)(Af + r0 * ASTR + kb);
                const uint32_t* ap8 = (const uint32_t*)(Af + (r0 + 8) * ASTR + kb);
                a[mt][0] = ap[tig];
                a[mt][1] = ap8[tig];
                a[mt][2] = ap[tig + 4];
                a[mt][3] = ap8[tig + 4];
            }
            uint32_t b[8][2];
#pragma unroll
            for (int nt = 0; nt < 8; nt++) {
                int br = 64 * wn + nt * 8 + gid;
                const uint32_t* bp = (const uint32_t*)(Bf + br * ASTR + kb);
                b[nt][0] = bp[tig];
                b[nt][1] = bp[tig + 4];
            }
#pragma unroll
            for (int mt = 0; mt < 4; mt++)
#pragma unroll
                for (int nt = 0; nt < 8; nt++)
                    mma16816(acc[mt][nt], a[mt], b[nt]);
        }
        __syncthreads();
    }

    // ---- epilogue ----
#pragma unroll
    for (int mt = 0; mt < 4; mt++) {
        int r0 = rowBase + 64 * wm + mt * 16 + gid;
#pragma unroll
        for (int nt = 0; nt < 8; nt++) {
            int gc = colBlk + 64 * wn + nt * 8 + 2 * tig;
#pragma unroll
            for (int half = 0; half < 2; half++) {
                int rr = r0 + half * 8;
                if (rr >= M) continue;
                float v0 = acc[mt][nt][half * 2 + 0];
                float v1 = acc[mt][nt][half * 2 + 1];
                if (SPLIT2) {
#pragma unroll
                    for (int q = 0; q < 2; q++) {
                        int col = gc + q;
                        float v = q ? v1 : v0;
                        if (col < 64) {
                            if (col < OUT_F) Ct2[(size_t)rr * T2S + col] = __float2half_rn(v);
                        } else {
                            int c2 = col - 64;
                            if (c2 < OUT_F) Caux[(size_t)rr * T2S + c2] = v + bias[c2];
                        }
                    }
                } else {
                    if (BIAS) { v0 += bias[gc]; v1 += bias[gc + 1]; }
                    if (WPRE) {
                        float* p = Cpre + (size_t)rr * ldC + gc;
                        p[0] = v0; p[1] = v1;
                    }
                    if (RELU) { v0 = fmaxf(v0, 0.f); v1 = fmaxf(v1, 0.f); }
                    if (WPLANES) {
                        __half2 hp = __floats2half2_rn(v0, v1);
                        *(__half2*)(Ch + (size_t)rr * ldC + gc) = hp;
                    }
                }
            }
        }
    }
}

// ---------------- launch ----------------------------------------------------
extern "C" void kernel_launch(void* const* d_in, const int* in_sizes, int n_in,
                              void* d_out, int out_size) {
    const float* x   = (const float*)d_in[0];
    const void*  ei  = d_in[1];
    const float* Wl0 = (const float*)d_in[2];
    const float* bl0 = (const float*)d_in[3];
    const float* Wr0 = (const float*)d_in[4];
    const float* Wl1 = (const float*)d_in[5];
    const float* bl1 = (const float*)d_in[6];
    const float* Wr1 = (const float*)d_in[7];
    const float* Wl2 = (const float*)d_in[8];
    const float* bl2 = (const float*)d_in[9];
    const float* Wr2 = (const float*)d_in[10];

    float* out  = (float*)d_out;
    float* hout = out + (size_t)NN * OUT_F;

    float* p_tmp;
    __half *xf, *aggf, *hf, *h2f, *t2, *wf;
    cudaGetSymbolAddress((void**)&p_tmp, g_tmp);
    cudaGetSymbolAddress((void**)&xf,   g_xf);
    cudaGetSymbolAddress((void**)&aggf, g_aggf);
    cudaGetSymbolAddress((void**)&hf,   g_hf);
    cudaGetSymbolAddress((void**)&h2f,  g_h2f);
    cudaGetSymbolAddress((void**)&t2,   g_t2);
    cudaGetSymbolAddress((void**)&wf,   g_wf);

    cudaFuncSetAttribute(k_mma<true,  true, true,  true,  false, false>,
                         cudaFuncAttributeMaxDynamicSharedMemorySize, GEMM_SMEM);
    cudaFuncSetAttribute(k_mma<true,  true, true,  true,  true,  false>,
                         cudaFuncAttributeMaxDynamicSharedMemorySize, GEMM_SMEM);
    cudaFuncSetAttribute(k_mma<false, true, false, false, false, true>,
                         cudaFuncAttributeMaxDynamicSharedMemorySize, GEMM_SMEM);

    const int MT = (NN + 127) / 128;               // 782
    const int AGG_BLKS = (NN + 7) / 8;

    // prep + CSR build; x plane conversion before first aggregation
    k_prep<<<(WB_TOTAL + 255) / 256, 256>>>((const int*)ei, Wl0, Wr0, Wl1, Wr1, Wl2, Wr2);
    k_cvt<<<(NN * IN_F / 4 + 255) / 256, 256>>>((const float4*)x, (uint2*)xf, NN * IN_F / 4);
    k_hist<<<(EE + 255) / 256, 256>>>(ei);
    k_scan1<<<(NN + 1023) / 1024, 1024>>>();
    k_scan23<<<(NN + 1023) / 1024, 1024>>>();
    k_scatter<<<(EE + 255) / 256, 256>>>(ei);

    // layer 0: relu(agg(x)@Wl0 + bl0 + x@Wr0) -> hf plane
    k_agg128<<<AGG_BLKS, 256>>>(xf, aggf);
    k_mma<true, true, true, true, false, false><<<dim3(MT, 2), 128, GEMM_SMEM>>>(
        aggf, IN_F, IN_F, wf + 0,     IN_F,
        xf,   IN_F, IN_F, wf + 32768, IN_F,
        bl0, hf, HID_F, nullptr, nullptr, nullptr, NN);

    // layer 1: pre -> hout (fp32); relu -> h2f plane
    k_agg256<<<AGG_BLKS, 256>>>(hf, aggf);
    k_mma<true, true, true, true, true, false><<<dim3(MT, 2), 128, GEMM_SMEM>>>(
        aggf, HID_F, HID_F, wf + 65536,  HID_F,
        hf,   HID_F, HID_F, wf + 131072, HID_F,
        bl1, h2f, HID_F, hout, nullptr, nullptr, NN);

    // layer 2 fused: t2 = h2@Wl2 (fp16) ; tmp = h2@Wr2 + bl2 (fp32)
    k_mma<false, true, false, false, false, true><<<dim3(MT, 1), 128, GEMM_SMEM>>>(
        h2f, HID_F, HID_F, wf + 196608, HID_F,
        nullptr, 0, 0, nullptr, 0,
        bl2, nullptr, T2S, nullptr, t2, p_tmp, NN);
    // out = mean-agg(t2) + tmp
    k_agg47_add<<<AGG_BLKS, 256>>>(t2, p_tmp, out);
}

// round 12
// speedup vs baseline: 2.0824x; 1.0108x over previous
#include <cuda_runtime.h>
#include <cuda_fp16.h>
#include <cstdint>

#define NN 100000
#define EE 1600000
#define IN_F 128
#define HID_F 256
#define OUT_F 47
#define T2S 48

// ---------------- scratch ---------------------------------------------------
__device__ float g_tmp[(size_t)NN * T2S];           // layer-2 direct term (fp32)
__device__ __align__(16) __half g_xf  [(size_t)NN * IN_F];
__device__ __align__(16) __half g_aggf[(size_t)NN * HID_F];
__device__ __align__(16) __half g_hf  [(size_t)NN * HID_F];
__device__ __align__(16) __half g_h2f [(size_t)NN * HID_F];
__device__ __align__(16) __half g_t2  [(size_t)NN * T2S];
__device__ int   g_count [NN];
__device__ float g_invdeg[NN];
__device__ int   g_rowptr[NN + 1];
__device__ int   g_cursor[NN];
__device__ int   g_csrsrc[EE];
__device__ int   g_bsums [128];
__device__ int   g_is64;

// weight table, fp16, transposed [N,K] row-major
#define WB_TOTAL 229376
__device__ __align__(16) __half g_wf[WB_TOTAL];

// ---------------- prep ------------------------------------------------------
__global__ void k_prep(const int* ei_raw,
                       const float* Wl0, const float* Wr0,
                       const float* Wl1, const float* Wr1,
                       const float* Wl2, const float* Wr2) {
    int idx = blockIdx.x * blockDim.x + threadIdx.x;
    if (idx < NN) g_count[idx] = 0;
    if (idx == 0) {
        int is64 = 1;
        for (int i = 0; i < 256; i++)
            if (ei_raw[2 * i + 1] != 0) { is64 = 0; break; }
        g_is64 = is64;
    }
    if (idx < WB_TOTAL) {
        float w;
        if (idx < 32768)       { int l = idx;          int n = l >> 7, k = l & 127; w = Wl0[k * 256 + n]; }
        else if (idx < 65536)  { int l = idx - 32768;  int n = l >> 7, k = l & 127; w = Wr0[k * 256 + n]; }
        else if (idx < 131072) { int l = idx - 65536;  int n = l >> 8, k = l & 255; w = Wl1[k * 256 + n]; }
        else if (idx < 196608) { int l = idx - 131072; int n = l >> 8, k = l & 255; w = Wr1[k * 256 + n]; }
        else if (idx < 212992) { int l = idx - 196608; int n = l >> 8, k = l & 255; w = (n < OUT_F) ? Wl2[k * OUT_F + n] : 0.f; }
        else                   { int l = idx - 212992; int n = l >> 8, k = l & 255; w = (n < OUT_F) ? Wr2[k * OUT_F + n] : 0.f; }
        g_wf[idx] = __float2half_rn(w);
    }
}

// x fp32 -> fp16 plane
__global__ void k_cvt(const float4* __restrict__ X, uint2* __restrict__ O, int n4) {
    int i = blockIdx.x * blockDim.x + threadIdx.x;
    if (i >= n4) return;
    float4 v = X[i];
    __half2 p0 = __floats2half2_rn(v.x, v.y);
    __half2 p1 = __floats2half2_rn(v.z, v.w);
    uint2 o;
    o.x = *(uint32_t*)&p0;
    o.y = *(uint32_t*)&p1;
    O[i] = o;
}

// ---------------- CSR build -------------------------------------------------
__device__ __forceinline__ int load_edge(const void* ei, long long idx, int is64) {
    if (is64) return (int)((const long long*)ei)[idx];
    return ((const int*)ei)[idx];
}

__global__ void k_hist(const void* ei) {
    int e = blockIdx.x * blockDim.x + threadIdx.x;
    if (e < EE) {
        int d = load_edge(ei, (long long)EE + e, g_is64);
        atomicAdd(&g_count[d], 1);
    }
}

__global__ void k_scan1() {
    __shared__ int sh[1024];
    int i = blockIdx.x * 1024 + threadIdx.x;
    int v = (i < NN) ? g_count[i] : 0;
    sh[threadIdx.x] = v;
    __syncthreads();
    for (int off = 1; off < 1024; off <<= 1) {
        int t = (threadIdx.x >= off) ? sh[threadIdx.x - off] : 0;
        __syncthreads();
        sh[threadIdx.x] += t;
        __syncthreads();
    }
    if (i < NN) g_rowptr[i] = sh[threadIdx.x] - v;
    if (threadIdx.x == 1023) g_bsums[blockIdx.x] = sh[1023];
}

__global__ void k_scan23() {
    __shared__ int base;
    if (threadIdx.x == 0) {
        int run = 0;
        for (int b = 0; b < (int)blockIdx.x; b++) run += g_bsums[b];
        base = run;
    }
    __syncthreads();
    int i = blockIdx.x * 1024 + threadIdx.x;
    if (i < NN) {
        int r = g_rowptr[i] + base;
        g_rowptr[i] = r;
        g_cursor[i] = r;
        g_invdeg[i] = 1.0f / (float)max(g_count[i], 1);
    }
    if (i == 0) g_rowptr[NN] = EE;
}

__global__ void k_scatter(const void* ei) {
    int e = blockIdx.x * blockDim.x + threadIdx.x;
    if (e < EE) {
        int is64 = g_is64;
        int d = load_edge(ei, (long long)EE + e, is64);
        int s = load_edge(ei, e, is64);
        int p = atomicAdd(&g_cursor[d], 1);
        g_csrsrc[p] = s;
    }
}

// ---------------- mean aggregation: fp16 -> fp16 plane ------------------------
// width 128: one uint2 (4 halfs) per lane per row
__global__ void k_agg128(const __half* __restrict__ X, __half* __restrict__ OF) {
    int w = (blockIdx.x * blockDim.x + threadIdx.x) >> 5;
    int lane = threadIdx.x & 31;
    if (w >= NN) return;
    int beg = g_rowptr[w], end = g_rowptr[w + 1];
    float4 acc = make_float4(0.f, 0.f, 0.f, 0.f);
    int e = beg;
    for (; e + 4 <= end; e += 4) {
        int s0 = g_csrsrc[e], s1 = g_csrsrc[e + 1];
        int s2 = g_csrsrc[e + 2], s3 = g_csrsrc[e + 3];
        uint2 u0 = ((const uint2*)(X + (size_t)s0 * IN_F))[lane];
        uint2 u1 = ((const uint2*)(X + (size_t)s1 * IN_F))[lane];
        uint2 u2 = ((const uint2*)(X + (size_t)s2 * IN_F))[lane];
        uint2 u3 = ((const uint2*)(X + (size_t)s3 * IN_F))[lane];
        float2 a0 = __half22float2(*(__half2*)&u0.x), b0 = __half22float2(*(__half2*)&u0.y);
        float2 a1 = __half22float2(*(__half2*)&u1.x), b1 = __half22float2(*(__half2*)&u1.y);
        float2 a2 = __half22float2(*(__half2*)&u2.x), b2 = __half22float2(*(__half2*)&u2.y);
        float2 a3 = __half22float2(*(__half2*)&u3.x), b3 = __half22float2(*(__half2*)&u3.y);
        acc.x += a0.x + a1.x + a2.x + a3.x;
        acc.y += a0.y + a1.y + a2.y + a3.y;
        acc.z += b0.x + b1.x + b2.x + b3.x;
        acc.w += b0.y + b1.y + b2.y + b3.y;
    }
    for (; e < end; e++) {
        uint2 u = ((const uint2*)(X + (size_t)g_csrsrc[e] * IN_F))[lane];
        float2 a = __half22float2(*(__half2*)&u.x), b = __half22float2(*(__half2*)&u.y);
        acc.x += a.x; acc.y += a.y; acc.z += b.x; acc.w += b.y;
    }
    float inv = g_invdeg[w];
    acc.x *= inv; acc.y *= inv; acc.z *= inv; acc.w *= inv;
    __half2 p0 = __floats2half2_rn(acc.x, acc.y);
    __half2 p1 = __floats2half2_rn(acc.z, acc.w);
    uint2 o;
    o.x = *(uint32_t*)&p0;
    o.y = *(uint32_t*)&p1;
    ((uint2*)(OF + (size_t)w * IN_F))[lane] = o;
}

// width 256: one uint4 (8 halfs) per lane per row
__global__ void k_agg256(const __half* __restrict__ X, __half* __restrict__ OF) {
    int w = (blockIdx.x * blockDim.x + threadIdx.x) >> 5;
    int lane = threadIdx.x & 31;
    if (w >= NN) return;
    int beg = g_rowptr[w], end = g_rowptr[w + 1];
    float acc[8];
#pragma unroll
    for (int j = 0; j < 8; j++) acc[j] = 0.f;
    int e = beg;
    for (; e + 4 <= end; e += 4) {
        int s0 = g_csrsrc[e], s1 = g_csrsrc[e + 1];
        int s2 = g_csrsrc[e + 2], s3 = g_csrsrc[e + 3];
        uint4 u0 = ((const uint4*)(X + (size_t)s0 * HID_F))[lane];
        uint4 u1 = ((const uint4*)(X + (size_t)s1 * HID_F))[lane];
        uint4 u2 = ((const uint4*)(X + (size_t)s2 * HID_F))[lane];
        uint4 u3 = ((const uint4*)(X + (size_t)s3 * HID_F))[lane];
#pragma unroll
        for (int q = 0; q < 4; q++) {
            uint32_t w0 = (&u0.x)[q], w1 = (&u1.x)[q], w2 = (&u2.x)[q], w3 = (&u3.x)[q];
            float2 f0 = __half22float2(*(__half2*)&w0);
            float2 f1 = __half22float2(*(__half2*)&w1);
            float2 f2 = __half22float2(*(__half2*)&w2);
            float2 f3 = __half22float2(*(__half2*)&w3);
            acc[2 * q]     += f0.x + f1.x + f2.x + f3.x;
            acc[2 * q + 1] += f0.y + f1.y + f2.y + f3.y;
        }
    }
    for (; e < end; e++) {
        uint4 u = ((const uint4*)(X + (size_t)g_csrsrc[e] * HID_F))[lane];
#pragma unroll
        for (int q = 0; q < 4; q++) {
            uint32_t ww = (&u.x)[q];
            float2 f = __half22float2(*(__half2*)&ww);
            acc[2 * q] += f.x; acc[2 * q + 1] += f.y;
        }
    }
    float inv = g_invdeg[w];
    uint4 o;
#pragma unroll
    for (int q = 0; q < 4; q++) {
        __half2 p = __floats2half2_rn(acc[2 * q] * inv, acc[2 * q + 1] * inv);
        (&o.x)[q] = *(uint32_t*)&p;
    }
    ((uint4*)(OF + (size_t)w * HID_F))[lane] = o;
}

// mean-agg over t2 (fp16, stride T2S) + tmp (fp32) -> out (stride 47)
__global__ void k_agg47_add(const __half* __restrict__ T2, const float* __restrict__ Tmp,
                            float* __restrict__ out) {
    int w = (blockIdx.x * blockDim.x + threadIdx.x) >> 5;
    int lane = threadIdx.x & 31;
    if (w >= NN || lane >= 24) return;
    int beg = g_rowptr[w], end = g_rowptr[w + 1];
    float a0 = 0.f, a1 = 0.f;
    int e = beg;
    for (; e + 4 <= end; e += 4) {
        int s0 = g_csrsrc[e], s1 = g_csrsrc[e + 1];
        int s2 = g_csrsrc[e + 2], s3 = g_csrsrc[e + 3];
        uint32_t u0 = *(const uint32_t*)(T2 + (size_t)s0 * T2S + lane * 2);
        uint32_t u1 = *(const uint32_t*)(T2 + (size_t)s1 * T2S + lane * 2);
        uint32_t u2 = *(const uint32_t*)(T2 + (size_t)s2 * T2S + lane * 2);
        uint32_t u3 = *(const uint32_t*)(T2 + (size_t)s3 * T2S + lane * 2);
        float2 f0 = __half22float2(*(__half2*)&u0);
        float2 f1 = __half22float2(*(__half2*)&u1);
        float2 f2 = __half22float2(*(__half2*)&u2);
        float2 f3 = __half22float2(*(__half2*)&u3);
        a0 += f0.x + f1.x + f2.x + f3.x;
        a1 += f0.y + f1.y + f2.y + f3.y;
    }
    for (; e < end; e++) {
        uint32_t u = *(const uint32_t*)(T2 + (size_t)g_csrsrc[e] * T2S + lane * 2);
        float2 f = __half22float2(*(__half2*)&u);
        a0 += f.x; a1 += f.y;
    }
    float inv = g_invdeg[w];
    const float* tr = Tmp + (size_t)w * T2S;
    float* orow = out + (size_t)w * OUT_F;
    int c0 = lane * 2, c1 = c0 + 1;
    orow[c0] = a0 * inv + tr[c0];
    if (c1 < OUT_F) orow[c1] = a1 * inv + tr[c1];
}

// ---------------- GEMM: fp16, ldmatrix feeds, 4-stage cp.async ---------------
__device__ __forceinline__ void mma16816(float* c, const uint32_t* a, const uint32_t* b) {
    asm volatile(
        "mma.sync.aligned.m16n8k16.row.col.f32.f16.f16.f32 "
        "{%0,%1,%2,%3}, {%4,%5,%6,%7}, {%8,%9}, {%0,%1,%2,%3};"
        : "+f"(c[0]), "+f"(c[1]), "+f"(c[2]), "+f"(c[3])
        : "r"(a[0]), "r"(a[1]), "r"(a[2]), "r"(a[3]), "r"(b[0]), "r"(b[1]));
}
__device__ __forceinline__ void ldmx4(uint32_t& r0, uint32_t& r1, uint32_t& r2, uint32_t& r3,
                                      uint32_t addr) {
    asm volatile("ldmatrix.sync.aligned.m8n8.x4.shared.b16 {%0,%1,%2,%3}, [%4];"
                 : "=r"(r0), "=r"(r1), "=r"(r2), "=r"(r3) : "r"(addr));
}
__device__ __forceinline__ void cp16(uint32_t dst, const void* src) {
    asm volatile("cp.async.cg.shared.global [%0], [%1], 16;" :: "r"(dst), "l"(src));
}
__device__ __forceinline__ void cp_commit() {
    asm volatile("cp.async.commit_group;" ::: "memory");
}
template <int N> __device__ __forceinline__ void cp_wait() {
    asm volatile("cp.async.wait_group %0;" :: "n"(N) : "memory");
}
__device__ __forceinline__ uint32_t smem_u32(const void* p) {
    uint32_t a;
    asm("{ .reg .u64 t; cvta.to.shared.u64 t, %1; cvt.u32.u64 %0, t; }"
        : "=r"(a) : "l"(p));
    return a;
}

#define APL 10240                        // plane: 128 rows x 80B (64B payload)
#define STAGE (2 * APL)                  // A, B
#define GEMM_SMEM (4 * STAGE)            // 81920 (4 stages)

template <bool DUAL, bool BIAS, bool RELU, bool WPLANES, bool WPRE, bool SPLIT2>
__global__ void __launch_bounds__(128, 2)
k_mma(const __half* __restrict__ A1, int ldA1, int K1,
      const __half* __restrict__ B1, int ldB1,
      const __half* __restrict__ A2, int ldA2, int K2,
      const __half* __restrict__ B2, int ldB2,
      const float* __restrict__ bias,
      __half* __restrict__ Ch, int ldC, float* __restrict__ Cpre,
      __half* __restrict__ Ct2, float* __restrict__ Caux, int M) {
    extern __shared__ __align__(16) char smem[];
    const uint32_t sbase = smem_u32(smem);

    const int tid  = threadIdx.x;
    const int wid  = tid >> 5;
    const int lane = tid & 31;
    const int wm   = wid >> 1;           // 2 warps along M (64 rows)
    const int wn   = wid & 1;            // 2 warps along N (64 cols)
    const int gid  = lane >> 2;
    const int tig  = lane & 3;

    const int rowBase = blockIdx.x * 128;
    const int colBlk  = blockIdx.y * 128;

    // ldmatrix per-lane byte offsets (within a plane, before kb shift)
    const uint32_t aoff = (uint32_t)((lane & 15) * 80 + (lane >> 4) * 16);
    const uint32_t boff = (uint32_t)(((lane & 7) + ((lane >> 4) & 1) * 8) * 80 +
                                     ((lane >> 3) & 1) * 16);

    float acc[4][8][4];
#pragma unroll
    for (int mt = 0; mt < 4; mt++)
#pragma unroll
        for (int nt = 0; nt < 8; nt++)
#pragma unroll
            for (int j = 0; j < 4; j++) acc[mt][nt][j] = 0.f;

    const int NC1 = K1 / 32;
    const int NC  = DUAL ? NC1 + K2 / 32 : NC1;

    auto issue = [&](int c) {
        const uint32_t sb = sbase + (c & 3) * STAGE;
        const int seg = (DUAL && c >= NC1) ? 1 : 0;
        const int k0 = (c - (seg ? NC1 : 0)) * 32;
        const __half* A = seg ? A2 : A1;
        const __half* B = seg ? B2 : B1;
        const int ldA = seg ? ldA2 : ldA1;
        const int ldB = seg ? ldB2 : ldB1;
#pragma unroll
        for (int i = tid; i < 1024; i += 128) {
            int p = i >> 9, r = (i >> 2) & 127, ch = i & 3;
            const __half* g;
            if (p == 0) {
                int gr = min(rowBase + r, M - 1);
                g = A + (size_t)gr * ldA + k0 + ch * 8;
            } else {
                g = B + (size_t)(colBlk + r) * ldB + k0 + ch * 8;
            }
            cp16(sb + p * APL + r * 80 + ch * 16, g);
        }
        cp_commit();
    };

    issue(0);
    issue(1);                            // NC >= 8 always
    for (int c = 0; c < NC; c++) {
        if (c + 2 < NC)      { issue(c + 2); cp_wait<2>(); }
        else if (c + 1 < NC) { cp_wait<1>(); }
        else                 { cp_wait<0>(); }
        __syncthreads();                 // single barrier per chunk (4-stage ring)
        const uint32_t sA = sbase + (c & 3) * STAGE;
        const uint32_t sB = sA + APL;
#pragma unroll
        for (int ks = 0; ks < 2; ks++) {
            const uint32_t kshift = (uint32_t)(ks * 32);
            uint32_t a[4][4];
#pragma unroll
            for (int mt = 0; mt < 4; mt++) {
                uint32_t addr = sA + (uint32_t)((64 * wm + mt * 16) * 80) + aoff + kshift;
                ldmx4(a[mt][0], a[mt][1], a[mt][2], a[mt][3], addr);
            }
            uint32_t b[8][2];
#pragma unroll
            for (int ntp = 0; ntp < 4; ntp++) {
                uint32_t addr = sB + (uint32_t)((64 * wn + ntp * 16) * 80) + boff + kshift;
                ldmx4(b[2 * ntp][0], b[2 * ntp][1], b[2 * ntp + 1][0], b[2 * ntp + 1][1], addr);
            }
#pragma unroll
            for (int mt = 0; mt < 4; mt++)
#pragma unroll
                for (int nt = 0; nt < 8; nt++)
                    mma16816(acc[mt][nt], a[mt], b[nt]);
        }
    }

    // ---- epilogue ----
#pragma unroll
    for (int mt = 0; mt < 4; mt++) {
        int r0 = rowBase + 64 * wm + mt * 16 + gid;
#pragma unroll
        for (int nt = 0; nt < 8; nt++) {
            int gc = colBlk + 64 * wn + nt * 8 + 2 * tig;
#pragma unroll
            for (int half = 0; half < 2; half++) {
                int rr = r0 + half * 8;
                if (rr >= M) continue;
                float v0 = acc[mt][nt][half * 2 + 0];
                float v1 = acc[mt][nt][half * 2 + 1];
                if (SPLIT2) {
#pragma unroll
                    for (int q = 0; q < 2; q++) {
                        int col = gc + q;
                        float v = q ? v1 : v0;
                        if (col < 64) {
                            if (col < OUT_F) Ct2[(size_t)rr * T2S + col] = __float2half_rn(v);
                        } else {
                            int c2 = col - 64;
                            if (c2 < OUT_F) Caux[(size_t)rr * T2S + c2] = v + bias[c2];
                        }
                    }
                } else {
                    if (BIAS) { v0 += bias[gc]; v1 += bias[gc + 1]; }
                    if (WPRE) {
                        float* p = Cpre + (size_t)rr * ldC + gc;
                        p[0] = v0; p[1] = v1;
                    }
                    if (RELU) { v0 = fmaxf(v0, 0.f); v1 = fmaxf(v1, 0.f); }
                    if (WPLANES) {
                        __half2 hp = __floats2half2_rn(v0, v1);
                        *(__half2*)(Ch + (size_t)rr * ldC + gc) = hp;
                    }
                }
            }
        }
    }
}

// ---------------- launch ----------------------------------------------------
extern "C" void kernel_launch(void* const* d_in, const int* in_sizes, int n_in,
                              void* d_out, int out_size) {
    const float* x   = (const float*)d_in[0];
    const void*  ei  = d_in[1];
    const float* Wl0 = (const float*)d_in[2];
    const float* bl0 = (const float*)d_in[3];
    const float* Wr0 = (const float*)d_in[4];
    const float* Wl1 = (const float*)d_in[5];
    const float* bl1 = (const float*)d_in[6];
    const float* Wr1 = (const float*)d_in[7];
    const float* Wl2 = (const float*)d_in[8];
    const float* bl2 = (const float*)d_in[9];
    const float* Wr2 = (const float*)d_in[10];

    float* out  = (float*)d_out;
    float* hout = out + (size_t)NN * OUT_F;

    float* p_tmp;
    __half *xf, *aggf, *hf, *h2f, *t2, *wf;
    cudaGetSymbolAddress((void**)&p_tmp, g_tmp);
    cudaGetSymbolAddress((void**)&xf,   g_xf);
    cudaGetSymbolAddress((void**)&aggf, g_aggf);
    cudaGetSymbolAddress((void**)&hf,   g_hf);
    cudaGetSymbolAddress((void**)&h2f,  g_h2f);
    cudaGetSymbolAddress((void**)&t2,   g_t2);
    cudaGetSymbolAddress((void**)&wf,   g_wf);

    cudaFuncSetAttribute(k_mma<true,  true, true,  true,  false, false>,
                         cudaFuncAttributeMaxDynamicSharedMemorySize, GEMM_SMEM);
    cudaFuncSetAttribute(k_mma<true,  true, true,  true,  true,  false>,
                         cudaFuncAttributeMaxDynamicSharedMemorySize, GEMM_SMEM);
    cudaFuncSetAttribute(k_mma<false, true, false, false, false, true>,
                         cudaFuncAttributeMaxDynamicSharedMemorySize, GEMM_SMEM);

    const int MT = (NN + 127) / 128;               // 782
    const int AGG_BLKS = (NN + 7) / 8;

    // prep + CSR build; x plane conversion before first aggregation
    k_prep<<<(WB_TOTAL + 255) / 256, 256>>>((const int*)ei, Wl0, Wr0, Wl1, Wr1, Wl2, Wr2);
    k_cvt<<<(NN * IN_F / 4 + 255) / 256, 256>>>((const float4*)x, (uint2*)xf, NN * IN_F / 4);
    k_hist<<<(EE + 255) / 256, 256>>>(ei);
    k_scan1<<<(NN + 1023) / 1024, 1024>>>();
    k_scan23<<<(NN + 1023) / 1024, 1024>>>();
    k_scatter<<<(EE + 255) / 256, 256>>>(ei);

    // layer 0: relu(agg(x)@Wl0 + bl0 + x@Wr0) -> hf plane
    k_agg128<<<AGG_BLKS, 256>>>(xf, aggf);
    k_mma<true, true, true, true, false, false><<<dim3(MT, 2), 128, GEMM_SMEM>>>(
        aggf, IN_F, IN_F, wf + 0,     IN_F,
        xf,   IN_F, IN_F, wf + 32768, IN_F,
        bl0, hf, HID_F, nullptr, nullptr, nullptr, NN);

    // layer 1: pre -> hout (fp32); relu -> h2f plane
    k_agg256<<<AGG_BLKS, 256>>>(hf, aggf);
    k_mma<true, true, true, true, true, false><<<dim3(MT, 2), 128, GEMM_SMEM>>>(
        aggf, HID_F, HID_F, wf + 65536,  HID_F,
        hf,   HID_F, HID_F, wf + 131072, HID_F,
        bl1, h2f, HID_F, hout, nullptr, nullptr, NN);

    // layer 2 fused: t2 = h2@Wl2 (fp16) ; tmp = h2@Wr2 + bl2 (fp32)
    k_mma<false, true, false, false, false, true><<<dim3(MT, 1), 128, GEMM_SMEM>>>(
        h2f, HID_F, HID_F, wf + 196608, HID_F,
        nullptr, 0, 0, nullptr, 0,
        bl2, nullptr, T2S, nullptr, t2, p_tmp, NN);
    // out = mean-agg(t2) + tmp
    k_agg47_add<<<AGG_BLKS, 256>>>(t2, p_tmp, out);
}